// round 1
// baseline (speedup 1.0000x reference)
#include <cuda_runtime.h>
#include <cstdint>

// ----------------------------------------------------------------------------
// UnifiedRadialMLP: 8 experts, per edge e and expert n:
//   h1 = silu(LN(W1[n] @ x[e] + b1[n]; g1,be1))          (128x64 matvec)
//   h2 = silu(LN(W2[n] @ h1 + b2[n]; g2,be2))            (128x128)
//   out[n,e,:] = W3[n] @ h2 + b3[n]                      (64x128)
//
// Strategy: expert-persistent CTAs. One CTA pins one expert's full weight set
// (128KB) + LN params in SMEM, loops over 64-edge tiles. Three register-tiled
// fp32 GEMMs fused with in-place LN+SiLU passes. 144 CTAs = 8 experts x 18
// slices, one wave at 1 CTA/SM (211KB smem).
// ----------------------------------------------------------------------------

namespace {

constexpr int N_EXP    = 8;
constexpr int D_IN     = 64;
constexpr int H        = 128;
constexpr int D_OUT    = 64;
constexpr int TE       = 64;        // edges per tile
constexpr int SLICES   = 18;        // blocks per expert
constexpr int NBLOCKS  = N_EXP * SLICES;   // 144
constexpr int NTHREADS = 256;
constexpr float LN_EPS = 1e-5f;

struct __align__(16) Smem {
    float w1[D_IN * H];      // [k][h]   k-major
    float w2[H * H];         // [k][o]
    float w3[H * D_OUT];     // [k][o]
    float x [TE * D_IN];     // [e][k]
    float h1[TE * H];        // [e][h]
    float h2[TE * H];        // [e][h]
    float b1[H], g1[H], be1[H];
    float b2[H], g2[H], be2[H];
    float b3[D_OUT];
};

__device__ __forceinline__ float silu_f(float v) {
    // v * sigmoid(v) == v / (1 + e^-v); __expf is plenty accurate for 1e-3 tol.
    return v / (1.0f + __expf(-v));
}

// In-place LayerNorm (+affine) + SiLU over rows of buf[TE][H].
// One warp per row; lane handles 4 contiguous channels (float4).
__device__ __forceinline__ void ln_silu_inplace(float* __restrict__ buf,
                                                const float* __restrict__ g,
                                                const float* __restrict__ be,
                                                int warp, int lane) {
    const float4 gv = *reinterpret_cast<const float4*>(&g[lane * 4]);
    const float4 bv = *reinterpret_cast<const float4*>(&be[lane * 4]);
    #pragma unroll 2
    for (int r = warp; r < TE; r += NTHREADS / 32) {
        float4 v = *reinterpret_cast<float4*>(&buf[r * H + lane * 4]);
        float s = v.x + v.y + v.z + v.w;
        float q = v.x * v.x + v.y * v.y + v.z * v.z + v.w * v.w;
        #pragma unroll
        for (int m = 16; m >= 1; m >>= 1) {
            s += __shfl_xor_sync(0xffffffffu, s, m);
            q += __shfl_xor_sync(0xffffffffu, q, m);
        }
        const float mu   = s * (1.0f / (float)H);
        const float var  = fmaf(-mu, mu, q * (1.0f / (float)H));
        const float rstd = rsqrtf(var + LN_EPS);
        v.x = silu_f(fmaf((v.x - mu) * rstd, gv.x, bv.x));
        v.y = silu_f(fmaf((v.y - mu) * rstd, gv.y, bv.y));
        v.z = silu_f(fmaf((v.z - mu) * rstd, gv.z, bv.z));
        v.w = silu_f(fmaf((v.w - mu) * rstd, gv.w, bv.w));
        *reinterpret_cast<float4*>(&buf[r * H + lane * 4]) = v;
    }
}

__global__ void __launch_bounds__(NTHREADS, 1)
radial_mlp_kernel(const float* __restrict__ x_g,
                  const float* __restrict__ W1, const float* __restrict__ b1,
                  const float* __restrict__ g1, const float* __restrict__ be1,
                  const float* __restrict__ W2, const float* __restrict__ b2,
                  const float* __restrict__ g2, const float* __restrict__ be2,
                  const float* __restrict__ W3, const float* __restrict__ b3,
                  float* __restrict__ out, int E, int ntiles) {
    extern __shared__ __align__(16) char smem_raw[];
    Smem& sm = *reinterpret_cast<Smem*>(smem_raw);

    const int tid   = threadIdx.x;
    const int n     = blockIdx.x & 7;     // expert
    const int slice = blockIdx.x >> 3;    // 0..SLICES-1

    // ---- One-time: stage expert weights (k-major) + params into SMEM ----
    for (int idx = tid; idx < H * D_IN; idx += NTHREADS) {
        int hh = idx >> 6, k = idx & 63;
        sm.w1[k * H + hh] = W1[(n * H + hh) * D_IN + k];
    }
    for (int idx = tid; idx < H * H; idx += NTHREADS) {
        int o = idx >> 7, k = idx & 127;
        sm.w2[k * H + o] = W2[n * H * H + o * H + k];
    }
    for (int idx = tid; idx < D_OUT * H; idx += NTHREADS) {
        int o = idx >> 7, k = idx & 127;
        sm.w3[k * D_OUT + o] = W3[n * D_OUT * H + o * H + k];
    }
    if (tid < H) {
        sm.b1[tid]  = b1 [n * H + tid];
        sm.g1[tid]  = g1 [n * H + tid];
        sm.be1[tid] = be1[n * H + tid];
        sm.b2[tid]  = b2 [n * H + tid];
        sm.g2[tid]  = g2 [n * H + tid];
        sm.be2[tid] = be2[n * H + tid];
    }
    if (tid < D_OUT) sm.b3[tid] = b3[n * D_OUT + tid];
    __syncthreads();

    const int tx   = tid & 15;   // output-column group
    const int ty   = tid >> 4;   // edge-row group (0..15)
    const int warp = tid >> 5;
    const int lane = tid & 31;

    for (int tile = slice; tile < ntiles; tile += SLICES) {
        const int e0 = tile * TE;

        // ---- Load x tile [TE][D_IN] (zero-padded past E) ----
        for (int f4 = tid; f4 < TE * (D_IN / 4); f4 += NTHREADS) {
            const int e  = f4 >> 4;
            const int kq = f4 & 15;
            const int ge = e0 + e;
            float4 v = make_float4(0.f, 0.f, 0.f, 0.f);
            if (ge < E)
                v = reinterpret_cast<const float4*>(x_g)[ge * (D_IN / 4) + kq];
            *reinterpret_cast<float4*>(&sm.x[e * D_IN + kq * 4]) = v;
        }
        __syncthreads();

        // ---- GEMM1: h1[64e][128h] = x[64e][64k] * w1[k][h], +b1 ----
        {
            float acc[4][8];
            #pragma unroll
            for (int i = 0; i < 4; i++)
                #pragma unroll
                for (int j = 0; j < 8; j++) acc[i][j] = 0.f;

            #pragma unroll 4
            for (int k = 0; k < D_IN; k++) {
                float xv[4];
                #pragma unroll
                for (int i = 0; i < 4; i++)
                    xv[i] = sm.x[(ty * 4 + i) * D_IN + k];   // warp broadcast
                const float4 wa = *reinterpret_cast<const float4*>(&sm.w1[k * H + tx * 4]);
                const float4 wb = *reinterpret_cast<const float4*>(&sm.w1[k * H + 64 + tx * 4]);
                #pragma unroll
                for (int i = 0; i < 4; i++) {
                    acc[i][0] = fmaf(xv[i], wa.x, acc[i][0]);
                    acc[i][1] = fmaf(xv[i], wa.y, acc[i][1]);
                    acc[i][2] = fmaf(xv[i], wa.z, acc[i][2]);
                    acc[i][3] = fmaf(xv[i], wa.w, acc[i][3]);
                    acc[i][4] = fmaf(xv[i], wb.x, acc[i][4]);
                    acc[i][5] = fmaf(xv[i], wb.y, acc[i][5]);
                    acc[i][6] = fmaf(xv[i], wb.z, acc[i][6]);
                    acc[i][7] = fmaf(xv[i], wb.w, acc[i][7]);
                }
            }
            const float4 ba = *reinterpret_cast<const float4*>(&sm.b1[tx * 4]);
            const float4 bb = *reinterpret_cast<const float4*>(&sm.b1[64 + tx * 4]);
            #pragma unroll
            for (int i = 0; i < 4; i++) {
                const int row = ty * 4 + i;
                float4 oa = make_float4(acc[i][0] + ba.x, acc[i][1] + ba.y,
                                        acc[i][2] + ba.z, acc[i][3] + ba.w);
                float4 ob = make_float4(acc[i][4] + bb.x, acc[i][5] + bb.y,
                                        acc[i][6] + bb.z, acc[i][7] + bb.w);
                *reinterpret_cast<float4*>(&sm.h1[row * H + tx * 4])      = oa;
                *reinterpret_cast<float4*>(&sm.h1[row * H + 64 + tx * 4]) = ob;
            }
        }
        __syncthreads();

        ln_silu_inplace(sm.h1, sm.g1, sm.be1, warp, lane);
        __syncthreads();

        // ---- GEMM2: h2[64e][128] = h1n[64e][128k] * w2[k][o], +b2 ----
        {
            float acc[4][8];
            #pragma unroll
            for (int i = 0; i < 4; i++)
                #pragma unroll
                for (int j = 0; j < 8; j++) acc[i][j] = 0.f;

            #pragma unroll 4
            for (int k = 0; k < H; k++) {
                float xv[4];
                #pragma unroll
                for (int i = 0; i < 4; i++)
                    xv[i] = sm.h1[(ty * 4 + i) * H + k];
                const float4 wa = *reinterpret_cast<const float4*>(&sm.w2[k * H + tx * 4]);
                const float4 wb = *reinterpret_cast<const float4*>(&sm.w2[k * H + 64 + tx * 4]);
                #pragma unroll
                for (int i = 0; i < 4; i++) {
                    acc[i][0] = fmaf(xv[i], wa.x, acc[i][0]);
                    acc[i][1] = fmaf(xv[i], wa.y, acc[i][1]);
                    acc[i][2] = fmaf(xv[i], wa.z, acc[i][2]);
                    acc[i][3] = fmaf(xv[i], wa.w, acc[i][3]);
                    acc[i][4] = fmaf(xv[i], wb.x, acc[i][4]);
                    acc[i][5] = fmaf(xv[i], wb.y, acc[i][5]);
                    acc[i][6] = fmaf(xv[i], wb.z, acc[i][6]);
                    acc[i][7] = fmaf(xv[i], wb.w, acc[i][7]);
                }
            }
            const float4 ba = *reinterpret_cast<const float4*>(&sm.b2[tx * 4]);
            const float4 bb = *reinterpret_cast<const float4*>(&sm.b2[64 + tx * 4]);
            #pragma unroll
            for (int i = 0; i < 4; i++) {
                const int row = ty * 4 + i;
                float4 oa = make_float4(acc[i][0] + ba.x, acc[i][1] + ba.y,
                                        acc[i][2] + ba.z, acc[i][3] + ba.w);
                float4 ob = make_float4(acc[i][4] + bb.x, acc[i][5] + bb.y,
                                        acc[i][6] + bb.z, acc[i][7] + bb.w);
                *reinterpret_cast<float4*>(&sm.h2[row * H + tx * 4])      = oa;
                *reinterpret_cast<float4*>(&sm.h2[row * H + 64 + tx * 4]) = ob;
            }
        }
        __syncthreads();

        ln_silu_inplace(sm.h2, sm.g2, sm.be2, warp, lane);
        __syncthreads();

        // ---- GEMM3: out[64e][64o] = h2n[64e][128k] * w3[k][o], +b3 -> GMEM ----
        {
            float acc[4][4];
            #pragma unroll
            for (int i = 0; i < 4; i++)
                #pragma unroll
                for (int j = 0; j < 4; j++) acc[i][j] = 0.f;

            #pragma unroll 4
            for (int k = 0; k < H; k++) {
                float xv[4];
                #pragma unroll
                for (int i = 0; i < 4; i++)
                    xv[i] = sm.h2[(ty * 4 + i) * H + k];
                const float4 w = *reinterpret_cast<const float4*>(&sm.w3[k * D_OUT + tx * 4]);
                #pragma unroll
                for (int i = 0; i < 4; i++) {
                    acc[i][0] = fmaf(xv[i], w.x, acc[i][0]);
                    acc[i][1] = fmaf(xv[i], w.y, acc[i][1]);
                    acc[i][2] = fmaf(xv[i], w.z, acc[i][2]);
                    acc[i][3] = fmaf(xv[i], w.w, acc[i][3]);
                }
            }
            const float4 bvec = *reinterpret_cast<const float4*>(&sm.b3[tx * 4]);
            #pragma unroll
            for (int i = 0; i < 4; i++) {
                const int ge = e0 + ty * 4 + i;
                if (ge < E) {
                    float4 o = make_float4(acc[i][0] + bvec.x, acc[i][1] + bvec.y,
                                           acc[i][2] + bvec.z, acc[i][3] + bvec.w);
                    *reinterpret_cast<float4*>(
                        &out[((size_t)n * (size_t)E + (size_t)ge) * D_OUT + tx * 4]) = o;
                }
            }
        }
        // No trailing barrier needed: next iteration's first write (sm.x) is
        // only read in GEMM1, which is separated by the post-load barrier.
    }
}

} // namespace

extern "C" void kernel_launch(void* const* d_in, const int* in_sizes, int n_in,
                              void* d_out, int out_size) {
    const float* x   = (const float*)d_in[0];
    const float* W1  = (const float*)d_in[1];
    const float* b1  = (const float*)d_in[2];
    const float* g1  = (const float*)d_in[3];
    const float* be1 = (const float*)d_in[4];
    const float* W2  = (const float*)d_in[5];
    const float* b2  = (const float*)d_in[6];
    const float* g2  = (const float*)d_in[7];
    const float* be2 = (const float*)d_in[8];
    const float* W3  = (const float*)d_in[9];
    const float* b3  = (const float*)d_in[10];
    float* out = (float*)d_out;

    const int E = in_sizes[0] / D_IN;
    const int ntiles = (E + TE - 1) / TE;

    // Not a stream op; legal during graph capture, idempotent.
    cudaFuncSetAttribute(radial_mlp_kernel,
                         cudaFuncAttributeMaxDynamicSharedMemorySize,
                         (int)sizeof(Smem));

    radial_mlp_kernel<<<NBLOCKS, NTHREADS, sizeof(Smem)>>>(
        x, W1, b1, g1, be1, W2, b2, g2, be2, W3, b3, out, E, ntiles);
}

// round 4
// speedup vs baseline: 2.2065x; 2.2065x over previous
#include <cuda_runtime.h>
#include <cstdint>

// ============================================================================
// UnifiedRadialMLP via legacy mma.sync (tf32, m16n8k8) — base sm_100 PTX.
// (tcgen05 is unavailable: harness compiles for sm_100 without the 'a' suffix.)
//
// 144 persistent CTAs = 8 experts x 18 slices. Each CTA stages its expert's
// weights once into SMEM (pair-permuted tf32 layout -> every mma fragment is
// one conflict-free LDS.64), then loops over 128-edge tiles:
//   GEMM1 (K=64,N=128) -> LN+SiLU -> GEMM2 (K=128,N=128) -> LN+SiLU
//   -> GEMM3 (K=128,N=64) -> +bias -> STG.64 coalesced.
// Each warp owns 16 edge rows x full N; LN stats reduce with 2 shfl_xor only.
// (Resubmission of R3 kernel: prior round died to a container-acquisition
//  failure with no kernel-attributable evidence; fragment mapping re-audited.)
// ============================================================================

namespace {

constexpr int D_IN  = 64;
constexpr int H     = 128;
constexpr int D_OUT = 64;
constexpr int TM    = 128;                 // edges per tile
constexpr int SLICES = 18;
constexpr int NBLOCKS = 8 * SLICES;        // 144
constexpr int NT    = 256;                 // 8 warps
constexpr float LN_EPS = 1e-5f;

// Padded strides (floats). stride/2 mod 32 == 4 -> LDS.64 bank = 4*row+t,
// distinct for all 32 lanes (row=g or g+8j, t=lane&3).
constexpr int XS = 72;     // K=64 operands
constexpr int HS = 136;    // K=128 operands

// SMEM layout in floats
constexpr int F_W1 = 0;                    // [128][XS]
constexpr int F_W2 = F_W1 + H * XS;        // [128][HS]
constexpr int F_W3 = F_W2 + H * HS;        // [64][HS]
constexpr int F_H  = F_W3 + D_OUT * HS;    // x (XS) / h (HS) union, [128][HS]
constexpr int F_B1 = F_H + TM * HS;
constexpr int F_G1 = F_B1 + H, F_BE1 = F_G1 + H;
constexpr int F_B2 = F_BE1 + H, F_G2 = F_B2 + H, F_BE2 = F_G2 + H;
constexpr int F_B3 = F_BE2 + H;
constexpr int SMEM_FLOATS = F_B3 + D_OUT;
constexpr int SMEM_BYTES  = SMEM_FLOATS * 4;   // ~210 KB

__device__ __forceinline__ uint32_t to_tf32(float f) {
    uint32_t r; asm("cvt.rna.tf32.f32 %0, %1;" : "=r"(r) : "f"(f)); return r;
}
// Pair-permutation of the K index inside each 8-block: position 2t holds k=t,
// position 2t+1 holds k=t+4, so (k, k+4) fragment pairs are one LDS.64.
__device__ __forceinline__ int perm(int k) {
    return ((k >> 3) << 3) | ((k & 3) << 1) | ((k >> 2) & 1);
}
__device__ __forceinline__ void mma8(float d[4],
                                     uint32_t a0, uint32_t a1, uint32_t a2, uint32_t a3,
                                     uint32_t b0, uint32_t b1) {
    asm volatile(
        "mma.sync.aligned.m16n8k8.row.col.f32.tf32.tf32.f32 "
        "{%0,%1,%2,%3}, {%4,%5,%6,%7}, {%8,%9}, {%0,%1,%2,%3};"
        : "+f"(d[0]), "+f"(d[1]), "+f"(d[2]), "+f"(d[3])
        : "r"(a0), "r"(a1), "r"(a2), "r"(a3), "r"(b0), "r"(b1));
}
__device__ __forceinline__ float silu_f(float v) { return v / (1.0f + __expf(-v)); }

__global__ void __launch_bounds__(NT, 1)
radial_mma(const float* __restrict__ x_g,
           const float* __restrict__ W1, const float* __restrict__ b1,
           const float* __restrict__ g1, const float* __restrict__ be1,
           const float* __restrict__ W2, const float* __restrict__ b2,
           const float* __restrict__ g2, const float* __restrict__ be2,
           const float* __restrict__ W3, const float* __restrict__ b3,
           float* __restrict__ out, int E, int ntiles) {
    extern __shared__ uint32_t sm[];
    float* smf = (float*)sm;

    const int tid  = threadIdx.x;
    const int warp = tid >> 5, lane = tid & 31;
    const int g = lane >> 2, t = lane & 3;        // mma quad coords
    const int n = blockIdx.x & 7, slice = blockIdx.x >> 3;
    const int m0 = warp * 16;                     // warp's edge-row base

    // ---- One-time: stage expert weights (perm layout, tf32) + params ----
    for (int i = tid; i < H * D_IN; i += NT) {
        const int r = i >> 6, k = i & 63;
        sm[F_W1 + r * XS + perm(k)] = to_tf32(W1[(size_t)(n * H + r) * D_IN + k]);
    }
    for (int i = tid; i < H * H; i += NT) {
        const int r = i >> 7, k = i & 127;
        sm[F_W2 + r * HS + perm(k)] = to_tf32(W2[(size_t)n * H * H + (size_t)r * H + k]);
    }
    for (int i = tid; i < D_OUT * H; i += NT) {
        const int r = i >> 7, k = i & 127;
        sm[F_W3 + r * HS + perm(k)] = to_tf32(W3[(size_t)n * D_OUT * H + (size_t)r * H + k]);
    }
    if (tid < H) {
        smf[F_B1 + tid]  = b1 [n * H + tid];
        smf[F_G1 + tid]  = g1 [n * H + tid];
        smf[F_BE1 + tid] = be1[n * H + tid];
        smf[F_B2 + tid]  = b2 [n * H + tid];
        smf[F_G2 + tid]  = g2 [n * H + tid];
        smf[F_BE2 + tid] = be2[n * H + tid];
    }
    if (tid < D_OUT) smf[F_B3 + tid] = b3[n * D_OUT + tid];
    __syncthreads();

    // Epilogue write positions for the quad's two columns (2t, 2t+1)
    const int p0  = ((2 * t) & 3) * 2 + ((2 * t) >> 2);
    const int p1  = ((2 * t + 1) & 3) * 2 + ((2 * t + 1) >> 2);
    const int ko0 = 2 * t;

    for (int tile = slice; tile < ntiles; tile += SLICES) {
        const int e0 = tile * TM;

        // ---- Stage x tile [128,64] (perm, tf32), zero-padded ----
        for (int i = tid; i < TM * D_IN; i += NT) {
            const int r = i >> 6, k = i & 63;
            const int ge = e0 + r;
            sm[F_H + r * XS + perm(k)] =
                (ge < E) ? to_tf32(x_g[(size_t)ge * D_IN + k]) : 0u;
        }
        __syncthreads();

        float acc[16][4];
        #pragma unroll
        for (int j = 0; j < 16; j++)
            acc[j][0] = acc[j][1] = acc[j][2] = acc[j][3] = 0.f;

        // ---- GEMM1: D1[16,128] = x @ W1^T, K=64 ----
        #pragma unroll 4
        for (int s = 0; s < 8; s++) {
            const int ko = 8 * s + ko0;
            const uint2 aA = *(const uint2*)(sm + F_H + (m0 + g)     * XS + ko);
            const uint2 aB = *(const uint2*)(sm + F_H + (m0 + g + 8) * XS + ko);
            #pragma unroll
            for (int j = 0; j < 16; j++) {
                const uint2 b = *(const uint2*)(sm + F_W1 + (8 * j + g) * XS + ko);
                mma8(acc[j], aA.x, aB.x, aA.y, aB.y, b.x, b.y);
            }
        }
        __syncthreads();   // all warps done reading x before h overwrites it

        // ---- Epilogue 1: +b1, LN, SiLU -> h (perm tf32) ----
        {
            float Sg = 0.f, Qg = 0.f, Sh = 0.f, Qh = 0.f;
            #pragma unroll
            for (int j = 0; j < 16; j++) {
                const float2 bb = *(const float2*)(smf + F_B1 + 8 * j + 2 * t);
                acc[j][0] += bb.x; acc[j][1] += bb.y;
                acc[j][2] += bb.x; acc[j][3] += bb.y;
                Sg += acc[j][0] + acc[j][1];
                Qg += acc[j][0] * acc[j][0] + acc[j][1] * acc[j][1];
                Sh += acc[j][2] + acc[j][3];
                Qh += acc[j][2] * acc[j][2] + acc[j][3] * acc[j][3];
            }
            #pragma unroll
            for (int m = 1; m <= 2; m <<= 1) {
                Sg += __shfl_xor_sync(~0u, Sg, m); Qg += __shfl_xor_sync(~0u, Qg, m);
                Sh += __shfl_xor_sync(~0u, Sh, m); Qh += __shfl_xor_sync(~0u, Qh, m);
            }
            const float mug = Sg * (1.f / H), muh = Sh * (1.f / H);
            const float rg = rsqrtf(fmaf(-mug, mug, Qg * (1.f / H)) + LN_EPS);
            const float rh = rsqrtf(fmaf(-muh, muh, Qh * (1.f / H)) + LN_EPS);
            #pragma unroll
            for (int j = 0; j < 16; j++) {
                const float2 gg = *(const float2*)(smf + F_G1  + 8 * j + 2 * t);
                const float2 be = *(const float2*)(smf + F_BE1 + 8 * j + 2 * t);
                sm[F_H + (m0 + g)     * HS + 8 * j + p0] =
                    to_tf32(silu_f(fmaf((acc[j][0] - mug) * rg, gg.x, be.x)));
                sm[F_H + (m0 + g)     * HS + 8 * j + p1] =
                    to_tf32(silu_f(fmaf((acc[j][1] - mug) * rg, gg.y, be.y)));
                sm[F_H + (m0 + g + 8) * HS + 8 * j + p0] =
                    to_tf32(silu_f(fmaf((acc[j][2] - muh) * rh, gg.x, be.x)));
                sm[F_H + (m0 + g + 8) * HS + 8 * j + p1] =
                    to_tf32(silu_f(fmaf((acc[j][3] - muh) * rh, gg.y, be.y)));
            }
        }
        __syncthreads();

        // ---- GEMM2: D2[16,128] = h @ W2^T, K=128 ----
        #pragma unroll
        for (int j = 0; j < 16; j++)
            acc[j][0] = acc[j][1] = acc[j][2] = acc[j][3] = 0.f;
        #pragma unroll 4
        for (int s = 0; s < 16; s++) {
            const int ko = 8 * s + ko0;
            const uint2 aA = *(const uint2*)(sm + F_H + (m0 + g)     * HS + ko);
            const uint2 aB = *(const uint2*)(sm + F_H + (m0 + g + 8) * HS + ko);
            #pragma unroll
            for (int j = 0; j < 16; j++) {
                const uint2 b = *(const uint2*)(sm + F_W2 + (8 * j + g) * HS + ko);
                mma8(acc[j], aA.x, aB.x, aA.y, aB.y, b.x, b.y);
            }
        }
        __syncthreads();   // all warps done reading h before it is overwritten

        // ---- Epilogue 2: +b2, LN, SiLU -> h (in place) ----
        {
            float Sg = 0.f, Qg = 0.f, Sh = 0.f, Qh = 0.f;
            #pragma unroll
            for (int j = 0; j < 16; j++) {
                const float2 bb = *(const float2*)(smf + F_B2 + 8 * j + 2 * t);
                acc[j][0] += bb.x; acc[j][1] += bb.y;
                acc[j][2] += bb.x; acc[j][3] += bb.y;
                Sg += acc[j][0] + acc[j][1];
                Qg += acc[j][0] * acc[j][0] + acc[j][1] * acc[j][1];
                Sh += acc[j][2] + acc[j][3];
                Qh += acc[j][2] * acc[j][2] + acc[j][3] * acc[j][3];
            }
            #pragma unroll
            for (int m = 1; m <= 2; m <<= 1) {
                Sg += __shfl_xor_sync(~0u, Sg, m); Qg += __shfl_xor_sync(~0u, Qg, m);
                Sh += __shfl_xor_sync(~0u, Sh, m); Qh += __shfl_xor_sync(~0u, Qh, m);
            }
            const float mug = Sg * (1.f / H), muh = Sh * (1.f / H);
            const float rg = rsqrtf(fmaf(-mug, mug, Qg * (1.f / H)) + LN_EPS);
            const float rh = rsqrtf(fmaf(-muh, muh, Qh * (1.f / H)) + LN_EPS);
            #pragma unroll
            for (int j = 0; j < 16; j++) {
                const float2 gg = *(const float2*)(smf + F_G2  + 8 * j + 2 * t);
                const float2 be = *(const float2*)(smf + F_BE2 + 8 * j + 2 * t);
                sm[F_H + (m0 + g)     * HS + 8 * j + p0] =
                    to_tf32(silu_f(fmaf((acc[j][0] - mug) * rg, gg.x, be.x)));
                sm[F_H + (m0 + g)     * HS + 8 * j + p1] =
                    to_tf32(silu_f(fmaf((acc[j][1] - mug) * rg, gg.y, be.y)));
                sm[F_H + (m0 + g + 8) * HS + 8 * j + p0] =
                    to_tf32(silu_f(fmaf((acc[j][2] - muh) * rh, gg.x, be.x)));
                sm[F_H + (m0 + g + 8) * HS + 8 * j + p1] =
                    to_tf32(silu_f(fmaf((acc[j][3] - muh) * rh, gg.y, be.y)));
            }
        }
        __syncthreads();

        // ---- GEMM3: D3[16,64] = h @ W3^T, K=128 ----
        float a3[8][4];
        #pragma unroll
        for (int j = 0; j < 8; j++)
            a3[j][0] = a3[j][1] = a3[j][2] = a3[j][3] = 0.f;
        #pragma unroll 4
        for (int s = 0; s < 16; s++) {
            const int ko = 8 * s + ko0;
            const uint2 aA = *(const uint2*)(sm + F_H + (m0 + g)     * HS + ko);
            const uint2 aB = *(const uint2*)(sm + F_H + (m0 + g + 8) * HS + ko);
            #pragma unroll
            for (int j = 0; j < 8; j++) {
                const uint2 b = *(const uint2*)(sm + F_W3 + (8 * j + g) * HS + ko);
                mma8(a3[j], aA.x, aB.x, aA.y, aB.y, b.x, b.y);
            }
        }

        // ---- Epilogue 3: +b3, coalesced STG.64 ----
        {
            const int ge  = e0 + m0 + g;
            const int ge8 = ge + 8;
            float* o0 = out + ((size_t)n * (size_t)E + (size_t)ge)  * D_OUT;
            float* o1 = out + ((size_t)n * (size_t)E + (size_t)ge8) * D_OUT;
            #pragma unroll
            for (int j = 0; j < 8; j++) {
                const float2 bb = *(const float2*)(smf + F_B3 + 8 * j + 2 * t);
                if (ge < E) {
                    float2 v = make_float2(a3[j][0] + bb.x, a3[j][1] + bb.y);
                    *(float2*)(o0 + 8 * j + 2 * t) = v;
                }
                if (ge8 < E) {
                    float2 v = make_float2(a3[j][2] + bb.x, a3[j][3] + bb.y);
                    *(float2*)(o1 + 8 * j + 2 * t) = v;
                }
            }
        }
        __syncthreads();   // h readers done before next tile stages x
    }
}

} // namespace

extern "C" void kernel_launch(void* const* d_in, const int* in_sizes, int n_in,
                              void* d_out, int out_size) {
    const float* x   = (const float*)d_in[0];
    const float* W1  = (const float*)d_in[1];
    const float* b1  = (const float*)d_in[2];
    const float* g1  = (const float*)d_in[3];
    const float* be1 = (const float*)d_in[4];
    const float* W2  = (const float*)d_in[5];
    const float* b2  = (const float*)d_in[6];
    const float* g2  = (const float*)d_in[7];
    const float* be2 = (const float*)d_in[8];
    const float* W3  = (const float*)d_in[9];
    const float* b3  = (const float*)d_in[10];
    float* out = (float*)d_out;

    const int E = in_sizes[0] / D_IN;
    const int ntiles = (E + TM - 1) / TM;

    cudaFuncSetAttribute(radial_mma,
                         cudaFuncAttributeMaxDynamicSharedMemorySize, SMEM_BYTES);

    radial_mma<<<NBLOCKS, NT, SMEM_BYTES>>>(
        x, W1, b1, g1, be1, W2, b2, g2, be2, W3, b3, out, E, ntiles);
}

// round 5
// speedup vs baseline: 2.7079x; 1.2272x over previous
#include <cuda_runtime.h>
#include <cstdint>

// ============================================================================
// UnifiedRadialMLP via legacy mma.sync (tf32, m16n8k8) — base sm_100 PTX.
//
// R5 change vs R4: tile loop is now FULLY WARP-INDEPENDENT.
//  - GEMM1's A-operand (x) is loaded straight from GMEM into registers, so the
//    x SMEM staging buffer (which aliased h and forced block-wide barriers) is
//    gone.
//  - Each warp owns h rows [m0, m0+16): it is the only writer and only reader
//    of those rows. All in-loop __syncthreads become __syncwarp (cross-lane
//    STS->LDS ordering within the warp only).
//  - Warps drift across phases, overlapping epilogue FMA with other warps'
//    MMA + LDS: attacks the 29% issue / 19% tensor underutilization of R4.
// ============================================================================

namespace {

constexpr int D_IN  = 64;
constexpr int H     = 128;
constexpr int D_OUT = 64;
constexpr int TM    = 128;                 // edges per tile (16 per warp)
constexpr int SLICES = 18;
constexpr int NBLOCKS = 8 * SLICES;        // 144
constexpr int NT    = 256;                 // 8 warps
constexpr float LN_EPS = 1e-5f;

// Padded strides (floats). stride/2 mod 32 == 4 -> LDS.64 bank = 4*row+t,
// distinct for all 32 lanes.
constexpr int XS = 72;     // K=64 operands (W1)
constexpr int HS = 136;    // K=128 operands (W2, W3, h)

// SMEM layout in floats
constexpr int F_W1 = 0;                    // [128][XS]
constexpr int F_W2 = F_W1 + H * XS;        // [128][HS]
constexpr int F_W3 = F_W2 + H * HS;        // [64][HS]
constexpr int F_H  = F_W3 + D_OUT * HS;    // h only now, [128][HS]
constexpr int F_B1 = F_H + TM * HS;
constexpr int F_G1 = F_B1 + H, F_BE1 = F_G1 + H;
constexpr int F_B2 = F_BE1 + H, F_G2 = F_B2 + H, F_BE2 = F_G2 + H;
constexpr int F_B3 = F_BE2 + H;
constexpr int SMEM_FLOATS = F_B3 + D_OUT;
constexpr int SMEM_BYTES  = SMEM_FLOATS * 4;   // ~210 KB

__device__ __forceinline__ uint32_t to_tf32(float f) {
    uint32_t r; asm("cvt.rna.tf32.f32 %0, %1;" : "=r"(r) : "f"(f)); return r;
}
// Pair-permutation of the K index inside each 8-block: position 2t holds k=t,
// position 2t+1 holds k=t+4, so (k, k+4) fragment pairs are one LDS.64.
__device__ __forceinline__ int perm(int k) {
    return ((k >> 3) << 3) | ((k & 3) << 1) | ((k >> 2) & 1);
}
__device__ __forceinline__ void mma8(float d[4],
                                     uint32_t a0, uint32_t a1, uint32_t a2, uint32_t a3,
                                     uint32_t b0, uint32_t b1) {
    asm volatile(
        "mma.sync.aligned.m16n8k8.row.col.f32.tf32.tf32.f32 "
        "{%0,%1,%2,%3}, {%4,%5,%6,%7}, {%8,%9}, {%0,%1,%2,%3};"
        : "+f"(d[0]), "+f"(d[1]), "+f"(d[2]), "+f"(d[3])
        : "r"(a0), "r"(a1), "r"(a2), "r"(a3), "r"(b0), "r"(b1));
}
__device__ __forceinline__ float silu_f(float v) { return v / (1.0f + __expf(-v)); }

__global__ void __launch_bounds__(NT, 1)
radial_mma(const float* __restrict__ x_g,
           const float* __restrict__ W1, const float* __restrict__ b1,
           const float* __restrict__ g1, const float* __restrict__ be1,
           const float* __restrict__ W2, const float* __restrict__ b2,
           const float* __restrict__ g2, const float* __restrict__ be2,
           const float* __restrict__ W3, const float* __restrict__ b3,
           float* __restrict__ out, int E, int ntiles) {
    extern __shared__ uint32_t sm[];
    float* smf = (float*)sm;

    const int tid  = threadIdx.x;
    const int warp = tid >> 5, lane = tid & 31;
    const int g = lane >> 2, t = lane & 3;        // mma quad coords
    const int n = blockIdx.x & 7, slice = blockIdx.x >> 3;
    const int m0 = warp * 16;                     // warp's edge-row base

    // ---- One-time: stage expert weights (perm layout, tf32) + params ----
    for (int i = tid; i < H * D_IN; i += NT) {
        const int r = i >> 6, k = i & 63;
        sm[F_W1 + r * XS + perm(k)] = to_tf32(W1[(size_t)(n * H + r) * D_IN + k]);
    }
    for (int i = tid; i < H * H; i += NT) {
        const int r = i >> 7, k = i & 127;
        sm[F_W2 + r * HS + perm(k)] = to_tf32(W2[(size_t)n * H * H + (size_t)r * H + k]);
    }
    for (int i = tid; i < D_OUT * H; i += NT) {
        const int r = i >> 7, k = i & 127;
        sm[F_W3 + r * HS + perm(k)] = to_tf32(W3[(size_t)n * D_OUT * H + (size_t)r * H + k]);
    }
    if (tid < H) {
        smf[F_B1 + tid]  = b1 [n * H + tid];
        smf[F_G1 + tid]  = g1 [n * H + tid];
        smf[F_BE1 + tid] = be1[n * H + tid];
        smf[F_B2 + tid]  = b2 [n * H + tid];
        smf[F_G2 + tid]  = g2 [n * H + tid];
        smf[F_BE2 + tid] = be2[n * H + tid];
    }
    if (tid < D_OUT) smf[F_B3 + tid] = b3[n * D_OUT + tid];
    __syncthreads();   // only block-wide barrier: weights visible to all warps

    // Epilogue write positions for the quad's two columns (2t, 2t+1)
    const int p0  = ((2 * t) & 3) * 2 + ((2 * t) >> 2);
    const int p1  = ((2 * t + 1) & 3) * 2 + ((2 * t + 1) >> 2);
    const int ko0 = 2 * t;

    for (int tile = slice; tile < ntiles; tile += SLICES) {
        const int e0 = tile * TM;
        const int ge0 = e0 + m0 + g;       // row m0+g
        const int ge1 = ge0 + 8;           // row m0+g+8

        // ---- GEMM1 A-operand: x rows straight from GMEM (predicated) ----
        // Per k-step s the fragment is cols {8s+t, 8s+t+4} of both rows.
        uint32_t A0[8][2], A1[8][2];
        {
            const float* xr0 = x_g + (size_t)ge0 * D_IN;
            const float* xr1 = x_g + (size_t)ge1 * D_IN;
            const bool v0 = ge0 < E, v1 = ge1 < E;
            #pragma unroll
            for (int s = 0; s < 8; s++) {
                A0[s][0] = v0 ? to_tf32(xr0[8 * s + t])     : 0u;
                A0[s][1] = v0 ? to_tf32(xr0[8 * s + t + 4]) : 0u;
                A1[s][0] = v1 ? to_tf32(xr1[8 * s + t])     : 0u;
                A1[s][1] = v1 ? to_tf32(xr1[8 * s + t + 4]) : 0u;
            }
        }

        float acc[16][4];
        #pragma unroll
        for (int j = 0; j < 16; j++)
            acc[j][0] = acc[j][1] = acc[j][2] = acc[j][3] = 0.f;

        // ---- GEMM1: D1[16,128] = x @ W1^T, K=64 ----
        #pragma unroll 4
        for (int s = 0; s < 8; s++) {
            const int ko = 8 * s + ko0;
            #pragma unroll
            for (int j = 0; j < 16; j++) {
                const uint2 b = *(const uint2*)(sm + F_W1 + (8 * j + g) * XS + ko);
                mma8(acc[j], A0[s][0], A1[s][0], A0[s][1], A1[s][1], b.x, b.y);
            }
        }
        // h rows m0..m0+15 were last read in the previous tile's GEMM3;
        // order those reads before this tile's epilogue-1 writes (warp-local).
        __syncwarp();

        // ---- Epilogue 1: +b1, LN, SiLU -> h (perm tf32) ----
        {
            float Sg = 0.f, Qg = 0.f, Sh = 0.f, Qh = 0.f;
            #pragma unroll
            for (int j = 0; j < 16; j++) {
                const float2 bb = *(const float2*)(smf + F_B1 + 8 * j + 2 * t);
                acc[j][0] += bb.x; acc[j][1] += bb.y;
                acc[j][2] += bb.x; acc[j][3] += bb.y;
                Sg += acc[j][0] + acc[j][1];
                Qg += acc[j][0] * acc[j][0] + acc[j][1] * acc[j][1];
                Sh += acc[j][2] + acc[j][3];
                Qh += acc[j][2] * acc[j][2] + acc[j][3] * acc[j][3];
            }
            #pragma unroll
            for (int m = 1; m <= 2; m <<= 1) {
                Sg += __shfl_xor_sync(~0u, Sg, m); Qg += __shfl_xor_sync(~0u, Qg, m);
                Sh += __shfl_xor_sync(~0u, Sh, m); Qh += __shfl_xor_sync(~0u, Qh, m);
            }
            const float mug = Sg * (1.f / H), muh = Sh * (1.f / H);
            const float rg = rsqrtf(fmaf(-mug, mug, Qg * (1.f / H)) + LN_EPS);
            const float rh = rsqrtf(fmaf(-muh, muh, Qh * (1.f / H)) + LN_EPS);
            #pragma unroll
            for (int j = 0; j < 16; j++) {
                const float2 gg = *(const float2*)(smf + F_G1  + 8 * j + 2 * t);
                const float2 be = *(const float2*)(smf + F_BE1 + 8 * j + 2 * t);
                sm[F_H + (m0 + g)     * HS + 8 * j + p0] =
                    to_tf32(silu_f(fmaf((acc[j][0] - mug) * rg, gg.x, be.x)));
                sm[F_H + (m0 + g)     * HS + 8 * j + p1] =
                    to_tf32(silu_f(fmaf((acc[j][1] - mug) * rg, gg.y, be.y)));
                sm[F_H + (m0 + g + 8) * HS + 8 * j + p0] =
                    to_tf32(silu_f(fmaf((acc[j][2] - muh) * rh, gg.x, be.x)));
                sm[F_H + (m0 + g + 8) * HS + 8 * j + p1] =
                    to_tf32(silu_f(fmaf((acc[j][3] - muh) * rh, gg.y, be.y)));
            }
        }
        __syncwarp();   // epi-1 writes visible to this warp's GEMM2 loads

        // ---- GEMM2: D2[16,128] = h @ W2^T, K=128 ----
        #pragma unroll
        for (int j = 0; j < 16; j++)
            acc[j][0] = acc[j][1] = acc[j][2] = acc[j][3] = 0.f;
        #pragma unroll 4
        for (int s = 0; s < 16; s++) {
            const int ko = 8 * s + ko0;
            const uint2 aA = *(const uint2*)(sm + F_H + (m0 + g)     * HS + ko);
            const uint2 aB = *(const uint2*)(sm + F_H + (m0 + g + 8) * HS + ko);
            #pragma unroll
            for (int j = 0; j < 16; j++) {
                const uint2 b = *(const uint2*)(sm + F_W2 + (8 * j + g) * HS + ko);
                mma8(acc[j], aA.x, aB.x, aA.y, aB.y, b.x, b.y);
            }
        }
        __syncwarp();   // GEMM2 h-reads done before epi-2 overwrites h

        // ---- Epilogue 2: +b2, LN, SiLU -> h (in place) ----
        {
            float Sg = 0.f, Qg = 0.f, Sh = 0.f, Qh = 0.f;
            #pragma unroll
            for (int j = 0; j < 16; j++) {
                const float2 bb = *(const float2*)(smf + F_B2 + 8 * j + 2 * t);
                acc[j][0] += bb.x; acc[j][1] += bb.y;
                acc[j][2] += bb.x; acc[j][3] += bb.y;
                Sg += acc[j][0] + acc[j][1];
                Qg += acc[j][0] * acc[j][0] + acc[j][1] * acc[j][1];
                Sh += acc[j][2] + acc[j][3];
                Qh += acc[j][2] * acc[j][2] + acc[j][3] * acc[j][3];
            }
            #pragma unroll
            for (int m = 1; m <= 2; m <<= 1) {
                Sg += __shfl_xor_sync(~0u, Sg, m); Qg += __shfl_xor_sync(~0u, Qg, m);
                Sh += __shfl_xor_sync(~0u, Sh, m); Qh += __shfl_xor_sync(~0u, Qh, m);
            }
            const float mug = Sg * (1.f / H), muh = Sh * (1.f / H);
            const float rg = rsqrtf(fmaf(-mug, mug, Qg * (1.f / H)) + LN_EPS);
            const float rh = rsqrtf(fmaf(-muh, muh, Qh * (1.f / H)) + LN_EPS);
            #pragma unroll
            for (int j = 0; j < 16; j++) {
                const float2 gg = *(const float2*)(smf + F_G2  + 8 * j + 2 * t);
                const float2 be = *(const float2*)(smf + F_BE2 + 8 * j + 2 * t);
                sm[F_H + (m0 + g)     * HS + 8 * j + p0] =
                    to_tf32(silu_f(fmaf((acc[j][0] - mug) * rg, gg.x, be.x)));
                sm[F_H + (m0 + g)     * HS + 8 * j + p1] =
                    to_tf32(silu_f(fmaf((acc[j][1] - mug) * rg, gg.y, be.y)));
                sm[F_H + (m0 + g + 8) * HS + 8 * j + p0] =
                    to_tf32(silu_f(fmaf((acc[j][2] - muh) * rh, gg.x, be.x)));
                sm[F_H + (m0 + g + 8) * HS + 8 * j + p1] =
                    to_tf32(silu_f(fmaf((acc[j][3] - muh) * rh, gg.y, be.y)));
            }
        }
        __syncwarp();   // epi-2 writes visible to this warp's GEMM3 loads

        // ---- GEMM3: D3[16,64] = h @ W3^T, K=128 ----
        float a3[8][4];
        #pragma unroll
        for (int j = 0; j < 8; j++)
            a3[j][0] = a3[j][1] = a3[j][2] = a3[j][3] = 0.f;
        #pragma unroll 4
        for (int s = 0; s < 16; s++) {
            const int ko = 8 * s + ko0;
            const uint2 aA = *(const uint2*)(sm + F_H + (m0 + g)     * HS + ko);
            const uint2 aB = *(const uint2*)(sm + F_H + (m0 + g + 8) * HS + ko);
            #pragma unroll
            for (int j = 0; j < 8; j++) {
                const uint2 b = *(const uint2*)(sm + F_W3 + (8 * j + g) * HS + ko);
                mma8(a3[j], aA.x, aB.x, aA.y, aB.y, b.x, b.y);
            }
        }

        // ---- Epilogue 3: +b3, coalesced STG.64 ----
        {
            float* o0 = out + ((size_t)n * (size_t)E + (size_t)ge0) * D_OUT;
            float* o1 = out + ((size_t)n * (size_t)E + (size_t)ge1) * D_OUT;
            #pragma unroll
            for (int j = 0; j < 8; j++) {
                const float2 bb = *(const float2*)(smf + F_B3 + 8 * j + 2 * t);
                if (ge0 < E) {
                    float2 v = make_float2(a3[j][0] + bb.x, a3[j][1] + bb.y);
                    *(float2*)(o0 + 8 * j + 2 * t) = v;
                }
                if (ge1 < E) {
                    float2 v = make_float2(a3[j][2] + bb.x, a3[j][3] + bb.y);
                    *(float2*)(o1 + 8 * j + 2 * t) = v;
                }
            }
        }
        // (next iteration's first touch of h is epi-1, which is preceded by a
        //  __syncwarp ordering this tile's GEMM3 h-reads.)
    }
}

} // namespace

extern "C" void kernel_launch(void* const* d_in, const int* in_sizes, int n_in,
                              void* d_out, int out_size) {
    const float* x   = (const float*)d_in[0];
    const float* W1  = (const float*)d_in[1];
    const float* b1  = (const float*)d_in[2];
    const float* g1  = (const float*)d_in[3];
    const float* be1 = (const float*)d_in[4];
    const float* W2  = (const float*)d_in[5];
    const float* b2  = (const float*)d_in[6];
    const float* g2  = (const float*)d_in[7];
    const float* be2 = (const float*)d_in[8];
    const float* W3  = (const float*)d_in[9];
    const float* b3  = (const float*)d_in[10];
    float* out = (float*)d_out;

    const int E = in_sizes[0] / D_IN;
    const int ntiles = (E + TM - 1) / TM;

    cudaFuncSetAttribute(radial_mma,
                         cudaFuncAttributeMaxDynamicSharedMemorySize, SMEM_BYTES);

    radial_mma<<<NBLOCKS, NT, SMEM_BYTES>>>(
        x, W1, b1, g1, be1, W2, b2, g2, be2, W3, b3, out, E, ntiles);
}

// round 7
// speedup vs baseline: 3.4293x; 1.2664x over previous
#include <cuda_runtime.h>
#include <cstdint>

// ============================================================================
// UnifiedRadialMLP via legacy mma.sync (tf32, m16n8k8) — base sm_100 PTX.
//
// R6 vs R5:
//  - 10 warps / 320 threads, TM=160 (16 rows per warp unchanged): h buffer
//    160x136 floats -> total SMEM 231,680 B, still within the 227KB dynamic
//    limit, raising warps/SMSP from 2 to 2.5 (latency hiding was the binder:
//    issue=34.8%, no pipe >50%).
//  - Manual 1-step software pipeline: B fragments (and A pairs) for k-step s+1
//    are loaded while step s's MMAs issue, removing LDS latency from the
//    dependency chain (registers: 204/thread available, ~114 used before).
//  - silu uses __fdividef (MUFU.RCP, no refinement).
// ============================================================================

namespace {

constexpr int D_IN  = 64;
constexpr int H     = 128;
constexpr int D_OUT = 64;
constexpr int TM    = 160;                 // edges per tile (16 per warp)
constexpr int SLICES = 18;
constexpr int NBLOCKS = 8 * SLICES;        // 144
constexpr int NT    = 320;                 // 10 warps
constexpr float LN_EPS = 1e-5f;

// Padded strides (floats). stride/2 mod 32 == 4 -> LDS.64 bank = 4*row+t,
// distinct for all 32 lanes.
constexpr int XS = 72;     // K=64 operands (W1)
constexpr int HS = 136;    // K=128 operands (W2, W3, h)

// SMEM layout in floats
constexpr int F_W1 = 0;                    // [128][XS]
constexpr int F_W2 = F_W1 + H * XS;        // [128][HS]
constexpr int F_W3 = F_W2 + H * HS;        // [64][HS]
constexpr int F_H  = F_W3 + D_OUT * HS;    // h, [160][HS]
constexpr int F_B1 = F_H + TM * HS;
constexpr int F_G1 = F_B1 + H, F_BE1 = F_G1 + H;
constexpr int F_B2 = F_BE1 + H, F_G2 = F_B2 + H, F_BE2 = F_G2 + H;
constexpr int F_B3 = F_BE2 + H;
constexpr int SMEM_FLOATS = F_B3 + D_OUT;
constexpr int SMEM_BYTES  = SMEM_FLOATS * 4;   // 231,680 B <= 232,448 B

__device__ __forceinline__ uint32_t to_tf32(float f) {
    uint32_t r; asm("cvt.rna.tf32.f32 %0, %1;" : "=r"(r) : "f"(f)); return r;
}
// Pair-permutation of the K index inside each 8-block: position 2t holds k=t,
// position 2t+1 holds k=t+4, so (k, k+4) fragment pairs are one LDS.64.
__device__ __forceinline__ int perm(int k) {
    return ((k >> 3) << 3) | ((k & 3) << 1) | ((k >> 2) & 1);
}
__device__ __forceinline__ void mma8(float d[4],
                                     uint32_t a0, uint32_t a1, uint32_t a2, uint32_t a3,
                                     uint32_t b0, uint32_t b1) {
    asm volatile(
        "mma.sync.aligned.m16n8k8.row.col.f32.tf32.tf32.f32 "
        "{%0,%1,%2,%3}, {%4,%5,%6,%7}, {%8,%9}, {%0,%1,%2,%3};"
        : "+f"(d[0]), "+f"(d[1]), "+f"(d[2]), "+f"(d[3])
        : "r"(a0), "r"(a1), "r"(a2), "r"(a3), "r"(b0), "r"(b1));
}
__device__ __forceinline__ float silu_f(float v) {
    return __fdividef(v, 1.0f + __expf(-v));
}

__global__ void __launch_bounds__(NT, 1)
radial_mma(const float* __restrict__ x_g,
           const float* __restrict__ W1, const float* __restrict__ b1,
           const float* __restrict__ g1, const float* __restrict__ be1,
           const float* __restrict__ W2, const float* __restrict__ b2,
           const float* __restrict__ g2, const float* __restrict__ be2,
           const float* __restrict__ W3, const float* __restrict__ b3,
           float* __restrict__ out, int E, int ntiles) {
    extern __shared__ uint32_t sm[];
    float* smf = (float*)sm;

    const int tid  = threadIdx.x;
    const int warp = tid >> 5, lane = tid & 31;
    const int g = lane >> 2, t = lane & 3;        // mma quad coords
    const int n = blockIdx.x & 7, slice = blockIdx.x >> 3;
    const int m0 = warp * 16;                     // warp's edge-row base

    // ---- One-time: stage expert weights (perm layout, tf32) + params ----
    for (int i = tid; i < H * D_IN; i += NT) {
        const int r = i >> 6, k = i & 63;
        sm[F_W1 + r * XS + perm(k)] = to_tf32(W1[(size_t)(n * H + r) * D_IN + k]);
    }
    for (int i = tid; i < H * H; i += NT) {
        const int r = i >> 7, k = i & 127;
        sm[F_W2 + r * HS + perm(k)] = to_tf32(W2[(size_t)n * H * H + (size_t)r * H + k]);
    }
    for (int i = tid; i < D_OUT * H; i += NT) {
        const int r = i >> 7, k = i & 127;
        sm[F_W3 + r * HS + perm(k)] = to_tf32(W3[(size_t)n * D_OUT * H + (size_t)r * H + k]);
    }
    if (tid < H) {
        smf[F_B1 + tid]  = b1 [n * H + tid];
        smf[F_G1 + tid]  = g1 [n * H + tid];
        smf[F_BE1 + tid] = be1[n * H + tid];
        smf[F_B2 + tid]  = b2 [n * H + tid];
        smf[F_G2 + tid]  = g2 [n * H + tid];
        smf[F_BE2 + tid] = be2[n * H + tid];
    }
    if (tid < D_OUT) smf[F_B3 + tid] = b3[n * D_OUT + tid];
    __syncthreads();   // only block-wide barrier: weights visible to all warps

    // Epilogue write positions for the quad's two columns (2t, 2t+1)
    const int p0  = ((2 * t) & 3) * 2 + ((2 * t) >> 2);
    const int p1  = ((2 * t + 1) & 3) * 2 + ((2 * t + 1) >> 2);
    const int ko0 = 2 * t;

    for (int tile = slice; tile < ntiles; tile += SLICES) {
        const int e0 = tile * TM;
        const int ge0 = e0 + m0 + g;       // row m0+g
        const int ge1 = ge0 + 8;           // row m0+g+8

        // ---- GEMM1 A-operand: x rows straight from GMEM (predicated) ----
        uint32_t A0[8][2], A1[8][2];
        {
            const float* xr0 = x_g + (size_t)ge0 * D_IN;
            const float* xr1 = x_g + (size_t)ge1 * D_IN;
            const bool v0 = ge0 < E, v1 = ge1 < E;
            #pragma unroll
            for (int s = 0; s < 8; s++) {
                A0[s][0] = v0 ? to_tf32(xr0[8 * s + t])     : 0u;
                A0[s][1] = v0 ? to_tf32(xr0[8 * s + t + 4]) : 0u;
                A1[s][0] = v1 ? to_tf32(xr1[8 * s + t])     : 0u;
                A1[s][1] = v1 ? to_tf32(xr1[8 * s + t + 4]) : 0u;
            }
        }

        float acc[16][4];
        #pragma unroll
        for (int j = 0; j < 16; j++)
            acc[j][0] = acc[j][1] = acc[j][2] = acc[j][3] = 0.f;

        // ---- GEMM1: D1[16,128] = x @ W1^T, K=64 (B double-buffered) ----
        {
            uint2 bc[16];
            #pragma unroll
            for (int j = 0; j < 16; j++)
                bc[j] = *(const uint2*)(sm + F_W1 + (8 * j + g) * XS + ko0);
            #pragma unroll 4
            for (int s = 0; s < 8; s++) {
                uint2 bn[16];
                if (s < 7) {
                    const int ko = 8 * (s + 1) + ko0;
                    #pragma unroll
                    for (int j = 0; j < 16; j++)
                        bn[j] = *(const uint2*)(sm + F_W1 + (8 * j + g) * XS + ko);
                }
                #pragma unroll
                for (int j = 0; j < 16; j++)
                    mma8(acc[j], A0[s][0], A1[s][0], A0[s][1], A1[s][1],
                         bc[j].x, bc[j].y);
                if (s < 7) {
                    #pragma unroll
                    for (int j = 0; j < 16; j++) bc[j] = bn[j];
                }
            }
        }
        // h rows m0..m0+15 were last read in the previous tile's GEMM3;
        // order those reads before this tile's epilogue-1 writes (warp-local).
        __syncwarp();

        // ---- Epilogue 1: +b1, LN, SiLU -> h (perm tf32) ----
        {
            float Sg = 0.f, Qg = 0.f, Sh = 0.f, Qh = 0.f;
            #pragma unroll
            for (int j = 0; j < 16; j++) {
                const float2 bb = *(const float2*)(smf + F_B1 + 8 * j + 2 * t);
                acc[j][0] += bb.x; acc[j][1] += bb.y;
                acc[j][2] += bb.x; acc[j][3] += bb.y;
                Sg += acc[j][0] + acc[j][1];
                Qg += acc[j][0] * acc[j][0] + acc[j][1] * acc[j][1];
                Sh += acc[j][2] + acc[j][3];
                Qh += acc[j][2] * acc[j][2] + acc[j][3] * acc[j][3];
            }
            #pragma unroll
            for (int m = 1; m <= 2; m <<= 1) {
                Sg += __shfl_xor_sync(~0u, Sg, m); Qg += __shfl_xor_sync(~0u, Qg, m);
                Sh += __shfl_xor_sync(~0u, Sh, m); Qh += __shfl_xor_sync(~0u, Qh, m);
            }
            const float mug = Sg * (1.f / H), muh = Sh * (1.f / H);
            const float rg = rsqrtf(fmaf(-mug, mug, Qg * (1.f / H)) + LN_EPS);
            const float rh = rsqrtf(fmaf(-muh, muh, Qh * (1.f / H)) + LN_EPS);
            #pragma unroll
            for (int j = 0; j < 16; j++) {
                const float2 gg = *(const float2*)(smf + F_G1  + 8 * j + 2 * t);
                const float2 be = *(const float2*)(smf + F_BE1 + 8 * j + 2 * t);
                sm[F_H + (m0 + g)     * HS + 8 * j + p0] =
                    to_tf32(silu_f(fmaf((acc[j][0] - mug) * rg, gg.x, be.x)));
                sm[F_H + (m0 + g)     * HS + 8 * j + p1] =
                    to_tf32(silu_f(fmaf((acc[j][1] - mug) * rg, gg.y, be.y)));
                sm[F_H + (m0 + g + 8) * HS + 8 * j + p0] =
                    to_tf32(silu_f(fmaf((acc[j][2] - muh) * rh, gg.x, be.x)));
                sm[F_H + (m0 + g + 8) * HS + 8 * j + p1] =
                    to_tf32(silu_f(fmaf((acc[j][3] - muh) * rh, gg.y, be.y)));
            }
        }
        __syncwarp();   // epi-1 writes visible to this warp's GEMM2 loads

        // ---- GEMM2: D2[16,128] = h @ W2^T, K=128 (A+B double-buffered) ----
        #pragma unroll
        for (int j = 0; j < 16; j++)
            acc[j][0] = acc[j][1] = acc[j][2] = acc[j][3] = 0.f;
        {
            uint2 bc[16];
            uint2 aAc = *(const uint2*)(sm + F_H + (m0 + g)     * HS + ko0);
            uint2 aBc = *(const uint2*)(sm + F_H + (m0 + g + 8) * HS + ko0);
            #pragma unroll
            for (int j = 0; j < 16; j++)
                bc[j] = *(const uint2*)(sm + F_W2 + (8 * j + g) * HS + ko0);
            #pragma unroll 4
            for (int s = 0; s < 16; s++) {
                uint2 bn[16], aAn, aBn;
                if (s < 15) {
                    const int ko = 8 * (s + 1) + ko0;
                    aAn = *(const uint2*)(sm + F_H + (m0 + g)     * HS + ko);
                    aBn = *(const uint2*)(sm + F_H + (m0 + g + 8) * HS + ko);
                    #pragma unroll
                    for (int j = 0; j < 16; j++)
                        bn[j] = *(const uint2*)(sm + F_W2 + (8 * j + g) * HS + ko);
                }
                #pragma unroll
                for (int j = 0; j < 16; j++)
                    mma8(acc[j], aAc.x, aBc.x, aAc.y, aBc.y, bc[j].x, bc[j].y);
                if (s < 15) {
                    aAc = aAn; aBc = aBn;
                    #pragma unroll
                    for (int j = 0; j < 16; j++) bc[j] = bn[j];
                }
            }
        }
        __syncwarp();   // GEMM2 h-reads done before epi-2 overwrites h

        // ---- Epilogue 2: +b2, LN, SiLU -> h (in place) ----
        {
            float Sg = 0.f, Qg = 0.f, Sh = 0.f, Qh = 0.f;
            #pragma unroll
            for (int j = 0; j < 16; j++) {
                const float2 bb = *(const float2*)(smf + F_B2 + 8 * j + 2 * t);
                acc[j][0] += bb.x; acc[j][1] += bb.y;
                acc[j][2] += bb.x; acc[j][3] += bb.y;
                Sg += acc[j][0] + acc[j][1];
                Qg += acc[j][0] * acc[j][0] + acc[j][1] * acc[j][1];
                Sh += acc[j][2] + acc[j][3];
                Qh += acc[j][2] * acc[j][2] + acc[j][3] * acc[j][3];
            }
            #pragma unroll
            for (int m = 1; m <= 2; m <<= 1) {
                Sg += __shfl_xor_sync(~0u, Sg, m); Qg += __shfl_xor_sync(~0u, Qg, m);
                Sh += __shfl_xor_sync(~0u, Sh, m); Qh += __shfl_xor_sync(~0u, Qh, m);
            }
            const float mug = Sg * (1.f / H), muh = Sh * (1.f / H);
            const float rg = rsqrtf(fmaf(-mug, mug, Qg * (1.f / H)) + LN_EPS);
            const float rh = rsqrtf(fmaf(-muh, muh, Qh * (1.f / H)) + LN_EPS);
            #pragma unroll
            for (int j = 0; j < 16; j++) {
                const float2 gg = *(const float2*)(smf + F_G2  + 8 * j + 2 * t);
                const float2 be = *(const float2*)(smf + F_BE2 + 8 * j + 2 * t);
                sm[F_H + (m0 + g)     * HS + 8 * j + p0] =
                    to_tf32(silu_f(fmaf((acc[j][0] - mug) * rg, gg.x, be.x)));
                sm[F_H + (m0 + g)     * HS + 8 * j + p1] =
                    to_tf32(silu_f(fmaf((acc[j][1] - mug) * rg, gg.y, be.y)));
                sm[F_H + (m0 + g + 8) * HS + 8 * j + p0] =
                    to_tf32(silu_f(fmaf((acc[j][2] - muh) * rh, gg.x, be.x)));
                sm[F_H + (m0 + g + 8) * HS + 8 * j + p1] =
                    to_tf32(silu_f(fmaf((acc[j][3] - muh) * rh, gg.y, be.y)));
            }
        }
        __syncwarp();   // epi-2 writes visible to this warp's GEMM3 loads

        // ---- GEMM3: D3[16,64] = h @ W3^T, K=128 (A+B double-buffered) ----
        float a3[8][4];
        #pragma unroll
        for (int j = 0; j < 8; j++)
            a3[j][0] = a3[j][1] = a3[j][2] = a3[j][3] = 0.f;
        {
            uint2 bc[8];
            uint2 aAc = *(const uint2*)(sm + F_H + (m0 + g)     * HS + ko0);
            uint2 aBc = *(const uint2*)(sm + F_H + (m0 + g + 8) * HS + ko0);
            #pragma unroll
            for (int j = 0; j < 8; j++)
                bc[j] = *(const uint2*)(sm + F_W3 + (8 * j + g) * HS + ko0);
            #pragma unroll 4
            for (int s = 0; s < 16; s++) {
                uint2 bn[8], aAn, aBn;
                if (s < 15) {
                    const int ko = 8 * (s + 1) + ko0;
                    aAn = *(const uint2*)(sm + F_H + (m0 + g)     * HS + ko);
                    aBn = *(const uint2*)(sm + F_H + (m0 + g + 8) * HS + ko);
                    #pragma unroll
                    for (int j = 0; j < 8; j++)
                        bn[j] = *(const uint2*)(sm + F_W3 + (8 * j + g) * HS + ko);
                }
                #pragma unroll
                for (int j = 0; j < 8; j++)
                    mma8(a3[j], aAc.x, aBc.x, aAc.y, aBc.y, bc[j].x, bc[j].y);
                if (s < 15) {
                    aAc = aAn; aBc = aBn;
                    #pragma unroll
                    for (int j = 0; j < 8; j++) bc[j] = bn[j];
                }
            }
        }

        // ---- Epilogue 3: +b3, coalesced STG.64 ----
        {
            float* o0 = out + ((size_t)n * (size_t)E + (size_t)ge0) * D_OUT;
            float* o1 = out + ((size_t)n * (size_t)E + (size_t)ge1) * D_OUT;
            #pragma unroll
            for (int j = 0; j < 8; j++) {
                const float2 bb = *(const float2*)(smf + F_B3 + 8 * j + 2 * t);
                if (ge0 < E) {
                    float2 v = make_float2(a3[j][0] + bb.x, a3[j][1] + bb.y);
                    *(float2*)(o0 + 8 * j + 2 * t) = v;
                }
                if (ge1 < E) {
                    float2 v = make_float2(a3[j][2] + bb.x, a3[j][3] + bb.y);
                    *(float2*)(o1 + 8 * j + 2 * t) = v;
                }
            }
        }
        // (next iteration's first touch of h is epi-1, preceded by __syncwarp.)
    }
}

} // namespace

extern "C" void kernel_launch(void* const* d_in, const int* in_sizes, int n_in,
                              void* d_out, int out_size) {
    const float* x   = (const float*)d_in[0];
    const float* W1  = (const float*)d_in[1];
    const float* b1  = (const float*)d_in[2];
    const float* g1  = (const float*)d_in[3];
    const float* be1 = (const float*)d_in[4];
    const float* W2  = (const float*)d_in[5];
    const float* b2  = (const float*)d_in[6];
    const float* g2  = (const float*)d_in[7];
    const float* be2 = (const float*)d_in[8];
    const float* W3  = (const float*)d_in[9];
    const float* b3  = (const float*)d_in[10];
    float* out = (float*)d_out;

    const int E = in_sizes[0] / D_IN;
    const int ntiles = (E + TM - 1) / TM;

    cudaFuncSetAttribute(radial_mma,
                         cudaFuncAttributeMaxDynamicSharedMemorySize, SMEM_BYTES);

    radial_mma<<<NBLOCKS, NT, SMEM_BYTES>>>(
        x, W1, b1, g1, be1, W2, b2, g2, be2, W3, b3, out, E, ntiles);
}

// round 8
// speedup vs baseline: 4.0236x; 1.1733x over previous
#include <cuda_runtime.h>
#include <cuda_fp16.h>
#include <cstdint>

// ============================================================================
// UnifiedRadialMLP via legacy mma.sync (tf32, m16n8k8) — base sm_100 PTX.
//
// R7 vs R6:
//  - M=32 rows per warp (2 row-pairs per B fragment): halves the dominant
//    B-fragment LDS traffic per row (L1 was the top pipe at 62.9%).
//  - h activations stored in SMEM as fp16 (11-bit mantissa == tf32: zero
//    precision cost). h buffer halves -> 8 warps x 32 rows = 256-row tiles
//    fit in 214KB SMEM. A-fragment = one conflict-free LDS.32 (fp16x2 packs
//    k and k+4); cvt.f32.f16 yields exact tf32 operands.
//  - Manual double-buffer copies removed (ALU was 29.3%); k-loops fully
//    unrolled, ptxas schedules loads with the register slack.
// ============================================================================

namespace {

constexpr int D_IN  = 64;
constexpr int H     = 128;
constexpr int D_OUT = 64;
constexpr int TM    = 256;                 // rows per tile (32 per warp)
constexpr int SLICES = 18;
constexpr int NBLOCKS = 8 * SLICES;        // 144
constexpr int NT    = 256;                 // 8 warps
constexpr float LN_EPS = 1e-5f;

// tf32 weight strides (32-bit words). stride mod 32 == 8 -> LDS.64 conflict-free.
constexpr int XS = 72;     // W1 (K=64)
constexpr int HS = 136;    // W2, W3 (K=128)
// h stride in 32-bit words (=136 halves, 272B). 68 mod 32 == 4 -> LDS.32
// banks = 4g+4s+t: all 32 lanes distinct.
constexpr int HWS = 68;

// SMEM layout (32-bit word offsets)
constexpr int F_W1 = 0;                    // [128][XS]
constexpr int F_W2 = F_W1 + H * XS;        // [128][HS]
constexpr int F_W3 = F_W2 + H * HS;        // [64][HS]
constexpr int F_HW = F_W3 + D_OUT * HS;    // h fp16, [256][HWS words]
constexpr int F_B1 = F_HW + TM * HWS;
constexpr int F_G1 = F_B1 + H, F_BE1 = F_G1 + H;
constexpr int F_B2 = F_BE1 + H, F_G2 = F_B2 + H, F_BE2 = F_G2 + H;
constexpr int F_B3 = F_BE2 + H;
constexpr int SMEM_WORDS = F_B3 + D_OUT;
constexpr int SMEM_BYTES = SMEM_WORDS * 4;   // 214,272 B

__device__ __forceinline__ uint32_t to_tf32(float f) {
    uint32_t r; asm("cvt.rna.tf32.f32 %0, %1;" : "=r"(r) : "f"(f)); return r;
}
// Pair-permutation of K inside each 8-block for tf32 WEIGHTS: position 2t
// holds k=t, 2t+1 holds k=t+4 -> one LDS.64 per B fragment.
__device__ __forceinline__ int perm(int k) {
    return ((k >> 3) << 3) | ((k & 3) << 1) | ((k >> 2) & 1);
}
__device__ __forceinline__ void mma8(float d[4],
                                     uint32_t a0, uint32_t a1, uint32_t a2, uint32_t a3,
                                     uint32_t b0, uint32_t b1) {
    asm volatile(
        "mma.sync.aligned.m16n8k8.row.col.f32.tf32.tf32.f32 "
        "{%0,%1,%2,%3}, {%4,%5,%6,%7}, {%8,%9}, {%0,%1,%2,%3};"
        : "+f"(d[0]), "+f"(d[1]), "+f"(d[2]), "+f"(d[3])
        : "r"(a0), "r"(a1), "r"(a2), "r"(a3), "r"(b0), "r"(b1));
}
__device__ __forceinline__ float silu_f(float v) {
    return __fdividef(v, 1.0f + __expf(-v));
}
__device__ __forceinline__ uint32_t fu(float f) { return __float_as_uint(f); }

__global__ void __launch_bounds__(NT, 1)
radial_mma(const float* __restrict__ x_g,
           const float* __restrict__ W1, const float* __restrict__ b1,
           const float* __restrict__ g1, const float* __restrict__ be1,
           const float* __restrict__ W2, const float* __restrict__ b2,
           const float* __restrict__ g2, const float* __restrict__ be2,
           const float* __restrict__ W3, const float* __restrict__ b3,
           float* __restrict__ out, int E, int ntiles) {
    extern __shared__ uint32_t sm[];
    float*  smf = (float*)sm;
    __half* hsm = (__half*)(sm + F_HW);    // h region, indexed in halves

    const int tid  = threadIdx.x;
    const int warp = tid >> 5, lane = tid & 31;
    const int g = lane >> 2, t = lane & 3;        // mma quad coords
    const int n = blockIdx.x & 7, slice = blockIdx.x >> 3;
    const int m0 = warp * 32;                     // warp's edge-row base

    // ---- One-time: stage expert weights (perm layout, tf32) + params ----
    for (int i = tid; i < H * D_IN; i += NT) {
        const int r = i >> 6, k = i & 63;
        sm[F_W1 + r * XS + perm(k)] = to_tf32(W1[(size_t)(n * H + r) * D_IN + k]);
    }
    for (int i = tid; i < H * H; i += NT) {
        const int r = i >> 7, k = i & 127;
        sm[F_W2 + r * HS + perm(k)] = to_tf32(W2[(size_t)n * H * H + (size_t)r * H + k]);
    }
    for (int i = tid; i < D_OUT * H; i += NT) {
        const int r = i >> 7, k = i & 127;
        sm[F_W3 + r * HS + perm(k)] = to_tf32(W3[(size_t)n * D_OUT * H + (size_t)r * H + k]);
    }
    if (tid < H) {
        smf[F_B1 + tid]  = b1 [n * H + tid];
        smf[F_G1 + tid]  = g1 [n * H + tid];
        smf[F_BE1 + tid] = be1[n * H + tid];
        smf[F_B2 + tid]  = b2 [n * H + tid];
        smf[F_G2 + tid]  = g2 [n * H + tid];
        smf[F_BE2 + tid] = be2[n * H + tid];
    }
    if (tid < D_OUT) smf[F_B3 + tid] = b3[n * D_OUT + tid];
    __syncthreads();   // only block-wide barrier

    const int ko0 = 2 * t;
    // h half-index pieces for epilogue writes: col cc -> half 8j + 2*(cc&3) + (cc>>2)
    const int c0 = 2 * t, c1 = 2 * t + 1;
    const int hoff0 = 2 * (c0 & 3) + (c0 >> 2);
    const int hoff1 = 2 * (c1 & 3) + (c1 >> 2);
    // lane's 4 rows: m0+g+8r
    const int row[4] = { m0 + g, m0 + g + 8, m0 + g + 16, m0 + g + 24 };

    for (int tile = slice; tile < ntiles; tile += SLICES) {
        const int e0 = tile * TM;
        int  ge[4];  bool vr[4];
        #pragma unroll
        for (int r = 0; r < 4; r++) { ge[r] = e0 + row[r]; vr[r] = ge[r] < E; }

        // ==== GEMM1: D1[32,128] = x @ W1^T, K=64, two 4-step phases ====
        float acc[16][2][4];   // [j][row-pair][4]
        #pragma unroll
        for (int j = 0; j < 16; j++)
            #pragma unroll
            for (int p = 0; p < 2; p++)
                acc[j][p][0] = acc[j][p][1] = acc[j][p][2] = acc[j][p][3] = 0.f;

        {
            uint32_t A[4][4][2];   // [row][step-in-phase][k/k+4]
            #pragma unroll
            for (int ph = 0; ph < 2; ph++) {
                #pragma unroll
                for (int r = 0; r < 4; r++) {
                    const float* xr = x_g + (size_t)ge[r] * D_IN + 32 * ph;
                    #pragma unroll
                    for (int s = 0; s < 4; s++) {
                        A[r][s][0] = vr[r] ? to_tf32(xr[8 * s + t])     : 0u;
                        A[r][s][1] = vr[r] ? to_tf32(xr[8 * s + t + 4]) : 0u;
                    }
                }
                #pragma unroll
                for (int s = 0; s < 4; s++) {
                    const int ko = 8 * (4 * ph + s) + ko0;
                    #pragma unroll
                    for (int j = 0; j < 16; j++) {
                        const uint2 b = *(const uint2*)(sm + F_W1 + (8 * j + g) * XS + ko);
                        mma8(acc[j][0], A[0][s][0], A[1][s][0], A[0][s][1], A[1][s][1], b.x, b.y);
                        mma8(acc[j][1], A[2][s][0], A[3][s][0], A[2][s][1], A[3][s][1], b.x, b.y);
                    }
                }
            }
        }
        // previous tile's GEMM3 read these h rows; order before epi-1 writes.
        __syncwarp();

        // ==== Epilogue 1: +b1, LN, SiLU -> h (fp16) ====
        #pragma unroll
        for (int e = 0; e < 2; e++) {   // e==0: epi1 params, e==1 skipped (see below)
            if (e == 1) break;
        }
        {
            float S[4] = {0, 0, 0, 0}, Q[4] = {0, 0, 0, 0};
            #pragma unroll
            for (int j = 0; j < 16; j++) {
                const float2 bb = *(const float2*)(smf + F_B1 + 8 * j + c0);
                #pragma unroll
                for (int r = 0; r < 4; r++) {
                    float& u = acc[j][r >> 1][(r & 1) * 2];
                    float& w = acc[j][r >> 1][(r & 1) * 2 + 1];
                    u += bb.x; w += bb.y;
                    S[r] += u + w;
                    Q[r] += u * u + w * w;
                }
            }
            #pragma unroll
            for (int m = 1; m <= 2; m <<= 1)
                #pragma unroll
                for (int r = 0; r < 4; r++) {
                    S[r] += __shfl_xor_sync(~0u, S[r], m);
                    Q[r] += __shfl_xor_sync(~0u, Q[r], m);
                }
            float mu[4], rs[4];
            #pragma unroll
            for (int r = 0; r < 4; r++) {
                mu[r] = S[r] * (1.f / H);
                rs[r] = rsqrtf(fmaf(-mu[r], mu[r], Q[r] * (1.f / H)) + LN_EPS);
            }
            #pragma unroll
            for (int j = 0; j < 16; j++) {
                const float2 gg = *(const float2*)(smf + F_G1  + 8 * j + c0);
                const float2 be = *(const float2*)(smf + F_BE1 + 8 * j + c0);
                #pragma unroll
                for (int r = 0; r < 4; r++) {
                    const float u = acc[j][r >> 1][(r & 1) * 2];
                    const float w = acc[j][r >> 1][(r & 1) * 2 + 1];
                    const int hb = row[r] * 136 + 8 * j;
                    hsm[hb + hoff0] = __float2half_rn(silu_f(fmaf((u - mu[r]) * rs[r], gg.x, be.x)));
                    hsm[hb + hoff1] = __float2half_rn(silu_f(fmaf((w - mu[r]) * rs[r], gg.y, be.y)));
                }
            }
        }
        __syncwarp();   // epi-1 writes visible to this warp's GEMM2 loads

        // ==== GEMM2: D2[32,128] = h @ W2^T, K=128 ====
        #pragma unroll
        for (int j = 0; j < 16; j++)
            #pragma unroll
            for (int p = 0; p < 2; p++)
                acc[j][p][0] = acc[j][p][1] = acc[j][p][2] = acc[j][p][3] = 0.f;
        #pragma unroll
        for (int s = 0; s < 16; s++) {
            const int ko = 8 * s + ko0;
            float2 f[4];
            #pragma unroll
            for (int r = 0; r < 4; r++) {
                const uint32_t v = sm[F_HW + row[r] * HWS + 4 * s + t];
                f[r] = __half22float2(*(const __half2*)&v);   // (k, k+4), exact tf32
            }
            #pragma unroll
            for (int j = 0; j < 16; j++) {
                const uint2 b = *(const uint2*)(sm + F_W2 + (8 * j + g) * HS + ko);
                mma8(acc[j][0], fu(f[0].x), fu(f[1].x), fu(f[0].y), fu(f[1].y), b.x, b.y);
                mma8(acc[j][1], fu(f[2].x), fu(f[3].x), fu(f[2].y), fu(f[3].y), b.x, b.y);
            }
        }
        __syncwarp();   // GEMM2 h-reads done before epi-2 overwrites h

        // ==== Epilogue 2: +b2, LN, SiLU -> h (in place) ====
        {
            float S[4] = {0, 0, 0, 0}, Q[4] = {0, 0, 0, 0};
            #pragma unroll
            for (int j = 0; j < 16; j++) {
                const float2 bb = *(const float2*)(smf + F_B2 + 8 * j + c0);
                #pragma unroll
                for (int r = 0; r < 4; r++) {
                    float& u = acc[j][r >> 1][(r & 1) * 2];
                    float& w = acc[j][r >> 1][(r & 1) * 2 + 1];
                    u += bb.x; w += bb.y;
                    S[r] += u + w;
                    Q[r] += u * u + w * w;
                }
            }
            #pragma unroll
            for (int m = 1; m <= 2; m <<= 1)
                #pragma unroll
                for (int r = 0; r < 4; r++) {
                    S[r] += __shfl_xor_sync(~0u, S[r], m);
                    Q[r] += __shfl_xor_sync(~0u, Q[r], m);
                }
            float mu[4], rs[4];
            #pragma unroll
            for (int r = 0; r < 4; r++) {
                mu[r] = S[r] * (1.f / H);
                rs[r] = rsqrtf(fmaf(-mu[r], mu[r], Q[r] * (1.f / H)) + LN_EPS);
            }
            #pragma unroll
            for (int j = 0; j < 16; j++) {
                const float2 gg = *(const float2*)(smf + F_G2  + 8 * j + c0);
                const float2 be = *(const float2*)(smf + F_BE2 + 8 * j + c0);
                #pragma unroll
                for (int r = 0; r < 4; r++) {
                    const float u = acc[j][r >> 1][(r & 1) * 2];
                    const float w = acc[j][r >> 1][(r & 1) * 2 + 1];
                    const int hb = row[r] * 136 + 8 * j;
                    hsm[hb + hoff0] = __float2half_rn(silu_f(fmaf((u - mu[r]) * rs[r], gg.x, be.x)));
                    hsm[hb + hoff1] = __float2half_rn(silu_f(fmaf((w - mu[r]) * rs[r], gg.y, be.y)));
                }
            }
        }
        __syncwarp();   // epi-2 writes visible to this warp's GEMM3 loads

        // ==== GEMM3: D3[32,64] = h @ W3^T, K=128 ====
        float a3[8][2][4];
        #pragma unroll
        for (int j = 0; j < 8; j++)
            #pragma unroll
            for (int p = 0; p < 2; p++)
                a3[j][p][0] = a3[j][p][1] = a3[j][p][2] = a3[j][p][3] = 0.f;
        #pragma unroll
        for (int s = 0; s < 16; s++) {
            const int ko = 8 * s + ko0;
            float2 f[4];
            #pragma unroll
            for (int r = 0; r < 4; r++) {
                const uint32_t v = sm[F_HW + row[r] * HWS + 4 * s + t];
                f[r] = __half22float2(*(const __half2*)&v);
            }
            #pragma unroll
            for (int j = 0; j < 8; j++) {
                const uint2 b = *(const uint2*)(sm + F_W3 + (8 * j + g) * HS + ko);
                mma8(a3[j][0], fu(f[0].x), fu(f[1].x), fu(f[0].y), fu(f[1].y), b.x, b.y);
                mma8(a3[j][1], fu(f[2].x), fu(f[3].x), fu(f[2].y), fu(f[3].y), b.x, b.y);
            }
        }

        // ==== Epilogue 3: +b3, coalesced STG.64 ====
        #pragma unroll
        for (int r = 0; r < 4; r++) {
            if (vr[r]) {
                float* o = out + ((size_t)n * (size_t)E + (size_t)ge[r]) * D_OUT;
                #pragma unroll
                for (int j = 0; j < 8; j++) {
                    const float2 bb = *(const float2*)(smf + F_B3 + 8 * j + c0);
                    float2 v = make_float2(a3[j][r >> 1][(r & 1) * 2]     + bb.x,
                                           a3[j][r >> 1][(r & 1) * 2 + 1] + bb.y);
                    *(float2*)(o + 8 * j + c0) = v;
                }
            }
        }
        // next iteration's first h touch is epi-1, preceded by __syncwarp.
    }
}

} // namespace

extern "C" void kernel_launch(void* const* d_in, const int* in_sizes, int n_in,
                              void* d_out, int out_size) {
    const float* x   = (const float*)d_in[0];
    const float* W1  = (const float*)d_in[1];
    const float* b1  = (const float*)d_in[2];
    const float* g1  = (const float*)d_in[3];
    const float* be1 = (const float*)d_in[4];
    const float* W2  = (const float*)d_in[5];
    const float* b2  = (const float*)d_in[6];
    const float* g2  = (const float*)d_in[7];
    const float* be2 = (const float*)d_in[8];
    const float* W3  = (const float*)d_in[9];
    const float* b3  = (const float*)d_in[10];
    float* out = (float*)d_out;

    const int E = in_sizes[0] / D_IN;
    const int ntiles = (E + TM - 1) / TM;

    cudaFuncSetAttribute(radial_mma,
                         cudaFuncAttributeMaxDynamicSharedMemorySize, SMEM_BYTES);

    radial_mma<<<NBLOCKS, NT, SMEM_BYTES>>>(
        x, W1, b1, g1, be1, W2, b2, g2, be2, W3, b3, out, E, ntiles);
}

// round 11
// speedup vs baseline: 5.2320x; 1.3004x over previous
#include <cuda_runtime.h>
#include <cuda_fp16.h>
#include <cstdint>

// ============================================================================
// UnifiedRadialMLP via mma.sync m16n8k16 f16/f32-acc — base sm_100 PTX.
//
// R10 vs R8/R9 (which died twice, suspected ptxas/compile-time pathology from
// full unrolling): GEMM2/GEMM3 k-step loops rolled to unroll 2, cutting static
// code ~60%. Algorithm identical:
//  - fp16 inputs (same 11-bit mantissa as tf32), f32 accumulate.
//  - m16n8k16: 2x K per HMMA at 2x rate vs tf32 k8.
//  - fp16 weights (perm16 layout, stride==8 mod 32 words: LDS.64 conflict-free).
//  - TM=320 / 10 warps, 171KB SMEM, warp-independent tile loop.
// ============================================================================

namespace {

constexpr int D_IN  = 64;
constexpr int H     = 128;
constexpr int D_OUT = 64;
constexpr int TM    = 320;                 // rows per tile (32 per warp)
constexpr int SLICES = 18;
constexpr int NBLOCKS = 8 * SLICES;        // 144
constexpr int NT    = 320;                 // 10 warps
constexpr float LN_EPS = 1e-5f;

// Row strides in 32-bit WORDS. stride mod 32 == 8 -> LDS.64 start-words
// (8g+2t) distinct within each half-warp phase: conflict-free.
constexpr int W1S = 40;    // W1: K=64  -> 32 words data + 8 pad
constexpr int WS  = 72;    // W2/W3/h: K=128 -> 64 words data + 8 pad

// SMEM layout (32-bit word offsets)
constexpr int F_W1 = 0;                        // fp16 [128][W1S words]
constexpr int F_W2 = F_W1 + H * W1S;           // fp16 [128][WS]
constexpr int F_W3 = F_W2 + H * WS;            // fp16 [64][WS]
constexpr int F_H  = F_W3 + D_OUT * WS;        // fp16 [320][WS]
constexpr int F_B1 = F_H + TM * WS;            // f32 params
constexpr int F_G1 = F_B1 + H, F_BE1 = F_G1 + H;
constexpr int F_B2 = F_BE1 + H, F_G2 = F_B2 + H, F_BE2 = F_G2 + H;
constexpr int F_B3 = F_BE2 + H;
constexpr int SMEM_WORDS = F_B3 + D_OUT;
constexpr int SMEM_BYTES = SMEM_WORDS * 4;     // 171,264 B

// Half-index permutation within each 16-k block: pair p=(k>>1)&7 -> word
// 2(p&3)+(p>>2); LDS.64 at word 8s+2t yields halves (2t,2t+1),(2t+8,2t+9)
// = exactly (frag0, frag1) of the m16n8k16 A/B fragments.
__device__ __forceinline__ int perm16h(int k) {
    const int p = (k >> 1) & 7;
    return ((k >> 4) << 4) | ((p & 3) << 2) | (((p >> 2) & 1) << 1) | (k & 1);
}

__device__ __forceinline__ void mma16(float d[4],
                                      uint32_t a0, uint32_t a1, uint32_t a2, uint32_t a3,
                                      uint32_t b0, uint32_t b1) {
    asm volatile(
        "mma.sync.aligned.m16n8k16.row.col.f32.f16.f16.f32 "
        "{%0,%1,%2,%3}, {%4,%5,%6,%7}, {%8,%9}, {%0,%1,%2,%3};"
        : "+f"(d[0]), "+f"(d[1]), "+f"(d[2]), "+f"(d[3])
        : "r"(a0), "r"(a1), "r"(a2), "r"(a3), "r"(b0), "r"(b1));
}
__device__ __forceinline__ float silu_f(float v) {
    return __fdividef(v, 1.0f + __expf(-v));
}
__device__ __forceinline__ uint32_t pack2(float lo, float hi) {
    const __half2 h = __floats2half2_rn(lo, hi);
    return *(const uint32_t*)&h;
}

__global__ void __launch_bounds__(NT, 1)
radial_mma(const float* __restrict__ x_g,
           const float* __restrict__ W1, const float* __restrict__ b1,
           const float* __restrict__ g1, const float* __restrict__ be1,
           const float* __restrict__ W2, const float* __restrict__ b2,
           const float* __restrict__ g2, const float* __restrict__ be2,
           const float* __restrict__ W3, const float* __restrict__ b3,
           float* __restrict__ out, int E, int ntiles) {
    extern __shared__ uint32_t sm[];
    float*   smf = (float*)sm;
    __half*  w1h = (__half*)(sm + F_W1);
    __half*  w2h = (__half*)(sm + F_W2);
    __half*  w3h = (__half*)(sm + F_W3);
    __half2* hp2 = (__half2*)sm;           // word-indexed half2 view

    const int tid  = threadIdx.x;
    const int warp = tid >> 5, lane = tid & 31;
    const int g = lane >> 2, t = lane & 3;        // mma quad coords
    const int n = blockIdx.x & 7, slice = blockIdx.x >> 3;
    const int m0 = warp * 32;                     // warp's edge-row base

    // ---- One-time: stage expert weights (fp16 perm16 layout) + params ----
    for (int i = tid; i < H * D_IN; i += NT) {
        const int r = i >> 6, k = i & 63;
        w1h[r * (2 * W1S) + perm16h(k)] =
            __float2half_rn(W1[(size_t)(n * H + r) * D_IN + k]);
    }
    for (int i = tid; i < H * H; i += NT) {
        const int r = i >> 7, k = i & 127;
        w2h[r * (2 * WS) + perm16h(k)] =
            __float2half_rn(W2[(size_t)n * H * H + (size_t)r * H + k]);
    }
    for (int i = tid; i < D_OUT * H; i += NT) {
        const int r = i >> 7, k = i & 127;
        w3h[r * (2 * WS) + perm16h(k)] =
            __float2half_rn(W3[(size_t)n * D_OUT * H + (size_t)r * H + k]);
    }
    if (tid < H) {
        smf[F_B1 + tid]  = b1 [n * H + tid];
        smf[F_G1 + tid]  = g1 [n * H + tid];
        smf[F_BE1 + tid] = be1[n * H + tid];
        smf[F_B2 + tid]  = b2 [n * H + tid];
        smf[F_G2 + tid]  = g2 [n * H + tid];
        smf[F_BE2 + tid] = be2[n * H + tid];
    }
    if (tid < D_OUT) smf[F_B3 + tid] = b3[n * D_OUT + tid];
    __syncthreads();   // only block-wide barrier

    const int c0 = 2 * t;
    const int row[4] = { m0 + g, m0 + g + 8, m0 + g + 16, m0 + g + 24 };

    for (int tile = slice; tile < ntiles; tile += SLICES) {
        const int e0 = tile * TM;
        int  ge[4];  bool vr[4];
        #pragma unroll
        for (int r = 0; r < 4; r++) { ge[r] = e0 + row[r]; vr[r] = ge[r] < E; }

        // ==== GEMM1: D1[32,128] = x @ W1^T, K=64 (4 k16-steps) ====
        float acc[16][2][4];   // [j][row-pair][4]
        #pragma unroll
        for (int j = 0; j < 16; j++)
            #pragma unroll
            for (int p = 0; p < 2; p++)
                acc[j][p][0] = acc[j][p][1] = acc[j][p][2] = acc[j][p][3] = 0.f;

        #pragma unroll 2
        for (int s = 0; s < 4; s++) {
            uint32_t Aa[4], Ab[4];     // per row: halves (2t,2t+1), (2t+8,2t+9)
            #pragma unroll
            for (int r = 0; r < 4; r++) {
                if (vr[r]) {
                    const float* xr = x_g + (size_t)ge[r] * D_IN + 16 * s;
                    const float2 u = *(const float2*)(xr + c0);
                    const float2 v = *(const float2*)(xr + c0 + 8);
                    Aa[r] = pack2(u.x, u.y);
                    Ab[r] = pack2(v.x, v.y);
                } else { Aa[r] = 0u; Ab[r] = 0u; }
            }
            #pragma unroll
            for (int j = 0; j < 16; j++) {
                const uint2 b = *(const uint2*)(sm + F_W1 + (8 * j + g) * W1S + 8 * s + c0);
                mma16(acc[j][0], Aa[0], Aa[1], Ab[0], Ab[1], b.x, b.y);
                mma16(acc[j][1], Aa[2], Aa[3], Ab[2], Ab[3], b.x, b.y);
            }
        }
        // previous tile's GEMM3 read these h rows; order before epi-1 writes.
        __syncwarp();

        // ==== Epilogue 1: +b1, LN, SiLU -> h (fp16, perm16) ====
        {
            float S[4] = {0, 0, 0, 0}, Q[4] = {0, 0, 0, 0};
            #pragma unroll
            for (int j = 0; j < 16; j++) {
                const float2 bb = *(const float2*)(smf + F_B1 + 8 * j + c0);
                #pragma unroll
                for (int r = 0; r < 4; r++) {
                    float& u = acc[j][r >> 1][(r & 1) * 2];
                    float& w = acc[j][r >> 1][(r & 1) * 2 + 1];
                    u += bb.x; w += bb.y;
                    S[r] += u + w;
                    Q[r] += u * u + w * w;
                }
            }
            #pragma unroll
            for (int m = 1; m <= 2; m <<= 1)
                #pragma unroll
                for (int r = 0; r < 4; r++) {
                    S[r] += __shfl_xor_sync(~0u, S[r], m);
                    Q[r] += __shfl_xor_sync(~0u, Q[r], m);
                }
            float mu[4], rs[4];
            #pragma unroll
            for (int r = 0; r < 4; r++) {
                mu[r] = S[r] * (1.f / H);
                rs[r] = rsqrtf(fmaf(-mu[r], mu[r], Q[r] * (1.f / H)) + LN_EPS);
            }
            #pragma unroll
            for (int j = 0; j < 16; j++) {
                const float2 gg = *(const float2*)(smf + F_G1  + 8 * j + c0);
                const float2 be = *(const float2*)(smf + F_BE1 + 8 * j + c0);
                // cols (8j+2t, 8j+2t+1) -> word row*WS + 8*(j>>1) + 2t + (j&1)
                const int wj = 8 * (j >> 1) + c0 + (j & 1);
                #pragma unroll
                for (int r = 0; r < 4; r++) {
                    const float u = acc[j][r >> 1][(r & 1) * 2];
                    const float w = acc[j][r >> 1][(r & 1) * 2 + 1];
                    hp2[F_H + row[r] * WS + wj] = __floats2half2_rn(
                        silu_f(fmaf((u - mu[r]) * rs[r], gg.x, be.x)),
                        silu_f(fmaf((w - mu[r]) * rs[r], gg.y, be.y)));
                }
            }
        }
        __syncwarp();   // epi-1 writes visible to this warp's GEMM2 loads

        // ==== GEMM2: D2[32,128] = h @ W2^T, K=128 (8 k16-steps, rolled x2) ====
        #pragma unroll
        for (int j = 0; j < 16; j++)
            #pragma unroll
            for (int p = 0; p < 2; p++)
                acc[j][p][0] = acc[j][p][1] = acc[j][p][2] = acc[j][p][3] = 0.f;
        #pragma unroll 2
        for (int s = 0; s < 8; s++) {
            uint2 Hc[4];
            #pragma unroll
            for (int r = 0; r < 4; r++)
                Hc[r] = *(const uint2*)(sm + F_H + row[r] * WS + 8 * s + c0);
            #pragma unroll
            for (int j = 0; j < 16; j++) {
                const uint2 b = *(const uint2*)(sm + F_W2 + (8 * j + g) * WS + 8 * s + c0);
                mma16(acc[j][0], Hc[0].x, Hc[1].x, Hc[0].y, Hc[1].y, b.x, b.y);
                mma16(acc[j][1], Hc[2].x, Hc[3].x, Hc[2].y, Hc[3].y, b.x, b.y);
            }
        }
        __syncwarp();   // GEMM2 h-reads done before epi-2 overwrites h

        // ==== Epilogue 2: +b2, LN, SiLU -> h (in place) ====
        {
            float S[4] = {0, 0, 0, 0}, Q[4] = {0, 0, 0, 0};
            #pragma unroll
            for (int j = 0; j < 16; j++) {
                const float2 bb = *(const float2*)(smf + F_B2 + 8 * j + c0);
                #pragma unroll
                for (int r = 0; r < 4; r++) {
                    float& u = acc[j][r >> 1][(r & 1) * 2];
                    float& w = acc[j][r >> 1][(r & 1) * 2 + 1];
                    u += bb.x; w += bb.y;
                    S[r] += u + w;
                    Q[r] += u * u + w * w;
                }
            }
            #pragma unroll
            for (int m = 1; m <= 2; m <<= 1)
                #pragma unroll
                for (int r = 0; r < 4; r++) {
                    S[r] += __shfl_xor_sync(~0u, S[r], m);
                    Q[r] += __shfl_xor_sync(~0u, Q[r], m);
                }
            float mu[4], rs[4];
            #pragma unroll
            for (int r = 0; r < 4; r++) {
                mu[r] = S[r] * (1.f / H);
                rs[r] = rsqrtf(fmaf(-mu[r], mu[r], Q[r] * (1.f / H)) + LN_EPS);
            }
            #pragma unroll
            for (int j = 0; j < 16; j++) {
                const float2 gg = *(const float2*)(smf + F_G2  + 8 * j + c0);
                const float2 be = *(const float2*)(smf + F_BE2 + 8 * j + c0);
                const int wj = 8 * (j >> 1) + c0 + (j & 1);
                #pragma unroll
                for (int r = 0; r < 4; r++) {
                    const float u = acc[j][r >> 1][(r & 1) * 2];
                    const float w = acc[j][r >> 1][(r & 1) * 2 + 1];
                    hp2[F_H + row[r] * WS + wj] = __floats2half2_rn(
                        silu_f(fmaf((u - mu[r]) * rs[r], gg.x, be.x)),
                        silu_f(fmaf((w - mu[r]) * rs[r], gg.y, be.y)));
                }
            }
        }
        __syncwarp();   // epi-2 writes visible to this warp's GEMM3 loads

        // ==== GEMM3: D3[32,64] = h @ W3^T, K=128 (8 k16-steps, rolled x2) ====
        float a3[8][2][4];
        #pragma unroll
        for (int j = 0; j < 8; j++)
            #pragma unroll
            for (int p = 0; p < 2; p++)
                a3[j][p][0] = a3[j][p][1] = a3[j][p][2] = a3[j][p][3] = 0.f;
        #pragma unroll 2
        for (int s = 0; s < 8; s++) {
            uint2 Hc[4];
            #pragma unroll
            for (int r = 0; r < 4; r++)
                Hc[r] = *(const uint2*)(sm + F_H + row[r] * WS + 8 * s + c0);
            #pragma unroll
            for (int j = 0; j < 8; j++) {
                const uint2 b = *(const uint2*)(sm + F_W3 + (8 * j + g) * WS + 8 * s + c0);
                mma16(a3[j][0], Hc[0].x, Hc[1].x, Hc[0].y, Hc[1].y, b.x, b.y);
                mma16(a3[j][1], Hc[2].x, Hc[3].x, Hc[2].y, Hc[3].y, b.x, b.y);
            }
        }

        // ==== Epilogue 3: +b3, coalesced STG.64 ====
        #pragma unroll
        for (int r = 0; r < 4; r++) {
            if (vr[r]) {
                float* o = out + ((size_t)n * (size_t)E + (size_t)ge[r]) * D_OUT;
                #pragma unroll
                for (int j = 0; j < 8; j++) {
                    const float2 bb = *(const float2*)(smf + F_B3 + 8 * j + c0);
                    float2 v = make_float2(a3[j][r >> 1][(r & 1) * 2]     + bb.x,
                                           a3[j][r >> 1][(r & 1) * 2 + 1] + bb.y);
                    *(float2*)(o + 8 * j + c0) = v;
                }
            }
        }
        // next iteration's first h touch is epi-1, preceded by __syncwarp.
    }
}

} // namespace

extern "C" void kernel_launch(void* const* d_in, const int* in_sizes, int n_in,
                              void* d_out, int out_size) {
    const float* x   = (const float*)d_in[0];
    const float* W1  = (const float*)d_in[1];
    const float* b1  = (const float*)d_in[2];
    const float* g1  = (const float*)d_in[3];
    const float* be1 = (const float*)d_in[4];
    const float* W2  = (const float*)d_in[5];
    const float* b2  = (const float*)d_in[6];
    const float* g2  = (const float*)d_in[7];
    const float* be2 = (const float*)d_in[8];
    const float* W3  = (const float*)d_in[9];
    const float* b3  = (const float*)d_in[10];
    float* out = (float*)d_out;

    const int E = in_sizes[0] / D_IN;
    const int ntiles = (E + TM - 1) / TM;

    cudaFuncSetAttribute(radial_mma,
                         cudaFuncAttributeMaxDynamicSharedMemorySize, SMEM_BYTES);

    radial_mma<<<NBLOCKS, NT, SMEM_BYTES>>>(
        x, W1, b1, g1, be1, W2, b2, g2, be2, W3, b3, out, E, ntiles);
}

// round 12
// speedup vs baseline: 5.7815x; 1.1050x over previous
#include <cuda_runtime.h>
#include <cuda_fp16.h>
#include <cstdint>

// ============================================================================
// UnifiedRadialMLP via mma.sync m16n8k16 f16/f32-acc — base sm_100 PTX.
//
// R11 vs R10:
//  - 11 warps / TM=352 (SMEM 180.5KB, reg cap 186 vs 168 used): raises
//    warps/SMSP 2.5 -> 2.75 against the issue=48% latency exposure.
//  - GEMM2/GEMM3 k-loops unroll 4 (was 2): halves rolled-loop address ALU
//    (alu was 25.6%) while staying well under the full-unroll size that
//    previously broke compilation.
// Algorithm unchanged: fp16 inputs / f32 accumulate, perm16 fragment layout,
// warp-independent tile loop, LN stats via 2x shfl_xor.
// ============================================================================

namespace {

constexpr int D_IN  = 64;
constexpr int H     = 128;
constexpr int D_OUT = 64;
constexpr int TM    = 352;                 // rows per tile (32 per warp)
constexpr int SLICES = 18;
constexpr int NBLOCKS = 8 * SLICES;        // 144
constexpr int NT    = 352;                 // 11 warps
constexpr float LN_EPS = 1e-5f;

// Row strides in 32-bit WORDS. stride mod 32 == 8 -> LDS.64 start-words
// (8g+2t) distinct within each half-warp phase: conflict-free.
constexpr int W1S = 40;    // W1: K=64  -> 32 words data + 8 pad
constexpr int WS  = 72;    // W2/W3/h: K=128 -> 64 words data + 8 pad

// SMEM layout (32-bit word offsets)
constexpr int F_W1 = 0;                        // fp16 [128][W1S words]
constexpr int F_W2 = F_W1 + H * W1S;           // fp16 [128][WS]
constexpr int F_W3 = F_W2 + H * WS;            // fp16 [64][WS]
constexpr int F_H  = F_W3 + D_OUT * WS;        // fp16 [352][WS]
constexpr int F_B1 = F_H + TM * WS;            // f32 params
constexpr int F_G1 = F_B1 + H, F_BE1 = F_G1 + H;
constexpr int F_B2 = F_BE1 + H, F_G2 = F_B2 + H, F_BE2 = F_G2 + H;
constexpr int F_B3 = F_BE2 + H;
constexpr int SMEM_WORDS = F_B3 + D_OUT;
constexpr int SMEM_BYTES = SMEM_WORDS * 4;     // 180,480 B

// Half-index permutation within each 16-k block: pair p=(k>>1)&7 -> word
// 2(p&3)+(p>>2); LDS.64 at word 8s+2t yields halves (2t,2t+1),(2t+8,2t+9)
// = exactly (frag0, frag1) of the m16n8k16 A/B fragments.
__device__ __forceinline__ int perm16h(int k) {
    const int p = (k >> 1) & 7;
    return ((k >> 4) << 4) | ((p & 3) << 2) | (((p >> 2) & 1) << 1) | (k & 1);
}

__device__ __forceinline__ void mma16(float d[4],
                                      uint32_t a0, uint32_t a1, uint32_t a2, uint32_t a3,
                                      uint32_t b0, uint32_t b1) {
    asm volatile(
        "mma.sync.aligned.m16n8k16.row.col.f32.f16.f16.f32 "
        "{%0,%1,%2,%3}, {%4,%5,%6,%7}, {%8,%9}, {%0,%1,%2,%3};"
        : "+f"(d[0]), "+f"(d[1]), "+f"(d[2]), "+f"(d[3])
        : "r"(a0), "r"(a1), "r"(a2), "r"(a3), "r"(b0), "r"(b1));
}
__device__ __forceinline__ float silu_f(float v) {
    return __fdividef(v, 1.0f + __expf(-v));
}
__device__ __forceinline__ uint32_t pack2(float lo, float hi) {
    const __half2 h = __floats2half2_rn(lo, hi);
    return *(const uint32_t*)&h;
}

__global__ void __launch_bounds__(NT, 1)
radial_mma(const float* __restrict__ x_g,
           const float* __restrict__ W1, const float* __restrict__ b1,
           const float* __restrict__ g1, const float* __restrict__ be1,
           const float* __restrict__ W2, const float* __restrict__ b2,
           const float* __restrict__ g2, const float* __restrict__ be2,
           const float* __restrict__ W3, const float* __restrict__ b3,
           float* __restrict__ out, int E, int ntiles) {
    extern __shared__ uint32_t sm[];
    float*   smf = (float*)sm;
    __half*  w1h = (__half*)(sm + F_W1);
    __half*  w2h = (__half*)(sm + F_W2);
    __half*  w3h = (__half*)(sm + F_W3);
    __half2* hp2 = (__half2*)sm;           // word-indexed half2 view

    const int tid  = threadIdx.x;
    const int warp = tid >> 5, lane = tid & 31;
    const int g = lane >> 2, t = lane & 3;        // mma quad coords
    const int n = blockIdx.x & 7, slice = blockIdx.x >> 3;
    const int m0 = warp * 32;                     // warp's edge-row base

    // ---- One-time: stage expert weights (fp16 perm16 layout) + params ----
    for (int i = tid; i < H * D_IN; i += NT) {
        const int r = i >> 6, k = i & 63;
        w1h[r * (2 * W1S) + perm16h(k)] =
            __float2half_rn(W1[(size_t)(n * H + r) * D_IN + k]);
    }
    for (int i = tid; i < H * H; i += NT) {
        const int r = i >> 7, k = i & 127;
        w2h[r * (2 * WS) + perm16h(k)] =
            __float2half_rn(W2[(size_t)n * H * H + (size_t)r * H + k]);
    }
    for (int i = tid; i < D_OUT * H; i += NT) {
        const int r = i >> 7, k = i & 127;
        w3h[r * (2 * WS) + perm16h(k)] =
            __float2half_rn(W3[(size_t)n * D_OUT * H + (size_t)r * H + k]);
    }
    if (tid < H) {
        smf[F_B1 + tid]  = b1 [n * H + tid];
        smf[F_G1 + tid]  = g1 [n * H + tid];
        smf[F_BE1 + tid] = be1[n * H + tid];
        smf[F_B2 + tid]  = b2 [n * H + tid];
        smf[F_G2 + tid]  = g2 [n * H + tid];
        smf[F_BE2 + tid] = be2[n * H + tid];
    }
    if (tid < D_OUT) smf[F_B3 + tid] = b3[n * D_OUT + tid];
    __syncthreads();   // only block-wide barrier

    const int c0 = 2 * t;
    const int row[4] = { m0 + g, m0 + g + 8, m0 + g + 16, m0 + g + 24 };

    for (int tile = slice; tile < ntiles; tile += SLICES) {
        const int e0 = tile * TM;
        int  ge[4];  bool vr[4];
        #pragma unroll
        for (int r = 0; r < 4; r++) { ge[r] = e0 + row[r]; vr[r] = ge[r] < E; }

        // ==== GEMM1: D1[32,128] = x @ W1^T, K=64 (4 k16-steps) ====
        float acc[16][2][4];   // [j][row-pair][4]
        #pragma unroll
        for (int j = 0; j < 16; j++)
            #pragma unroll
            for (int p = 0; p < 2; p++)
                acc[j][p][0] = acc[j][p][1] = acc[j][p][2] = acc[j][p][3] = 0.f;

        #pragma unroll 2
        for (int s = 0; s < 4; s++) {
            uint32_t Aa[4], Ab[4];     // per row: halves (2t,2t+1), (2t+8,2t+9)
            #pragma unroll
            for (int r = 0; r < 4; r++) {
                if (vr[r]) {
                    const float* xr = x_g + (size_t)ge[r] * D_IN + 16 * s;
                    const float2 u = *(const float2*)(xr + c0);
                    const float2 v = *(const float2*)(xr + c0 + 8);
                    Aa[r] = pack2(u.x, u.y);
                    Ab[r] = pack2(v.x, v.y);
                } else { Aa[r] = 0u; Ab[r] = 0u; }
            }
            #pragma unroll
            for (int j = 0; j < 16; j++) {
                const uint2 b = *(const uint2*)(sm + F_W1 + (8 * j + g) * W1S + 8 * s + c0);
                mma16(acc[j][0], Aa[0], Aa[1], Ab[0], Ab[1], b.x, b.y);
                mma16(acc[j][1], Aa[2], Aa[3], Ab[2], Ab[3], b.x, b.y);
            }
        }
        // previous tile's GEMM3 read these h rows; order before epi-1 writes.
        __syncwarp();

        // ==== Epilogue 1: +b1, LN, SiLU -> h (fp16, perm16) ====
        {
            float S[4] = {0, 0, 0, 0}, Q[4] = {0, 0, 0, 0};
            #pragma unroll
            for (int j = 0; j < 16; j++) {
                const float2 bb = *(const float2*)(smf + F_B1 + 8 * j + c0);
                #pragma unroll
                for (int r = 0; r < 4; r++) {
                    float& u = acc[j][r >> 1][(r & 1) * 2];
                    float& w = acc[j][r >> 1][(r & 1) * 2 + 1];
                    u += bb.x; w += bb.y;
                    S[r] += u + w;
                    Q[r] += u * u + w * w;
                }
            }
            #pragma unroll
            for (int m = 1; m <= 2; m <<= 1)
                #pragma unroll
                for (int r = 0; r < 4; r++) {
                    S[r] += __shfl_xor_sync(~0u, S[r], m);
                    Q[r] += __shfl_xor_sync(~0u, Q[r], m);
                }
            float mu[4], rs[4];
            #pragma unroll
            for (int r = 0; r < 4; r++) {
                mu[r] = S[r] * (1.f / H);
                rs[r] = rsqrtf(fmaf(-mu[r], mu[r], Q[r] * (1.f / H)) + LN_EPS);
            }
            #pragma unroll
            for (int j = 0; j < 16; j++) {
                const float2 gg = *(const float2*)(smf + F_G1  + 8 * j + c0);
                const float2 be = *(const float2*)(smf + F_BE1 + 8 * j + c0);
                // cols (8j+2t, 8j+2t+1) -> word row*WS + 8*(j>>1) + 2t + (j&1)
                const int wj = 8 * (j >> 1) + c0 + (j & 1);
                #pragma unroll
                for (int r = 0; r < 4; r++) {
                    const float u = acc[j][r >> 1][(r & 1) * 2];
                    const float w = acc[j][r >> 1][(r & 1) * 2 + 1];
                    hp2[F_H + row[r] * WS + wj] = __floats2half2_rn(
                        silu_f(fmaf((u - mu[r]) * rs[r], gg.x, be.x)),
                        silu_f(fmaf((w - mu[r]) * rs[r], gg.y, be.y)));
                }
            }
        }
        __syncwarp();   // epi-1 writes visible to this warp's GEMM2 loads

        // ==== GEMM2: D2[32,128] = h @ W2^T, K=128 (8 k16-steps, unroll 4) ====
        #pragma unroll
        for (int j = 0; j < 16; j++)
            #pragma unroll
            for (int p = 0; p < 2; p++)
                acc[j][p][0] = acc[j][p][1] = acc[j][p][2] = acc[j][p][3] = 0.f;
        #pragma unroll 4
        for (int s = 0; s < 8; s++) {
            uint2 Hc[4];
            #pragma unroll
            for (int r = 0; r < 4; r++)
                Hc[r] = *(const uint2*)(sm + F_H + row[r] * WS + 8 * s + c0);
            #pragma unroll
            for (int j = 0; j < 16; j++) {
                const uint2 b = *(const uint2*)(sm + F_W2 + (8 * j + g) * WS + 8 * s + c0);
                mma16(acc[j][0], Hc[0].x, Hc[1].x, Hc[0].y, Hc[1].y, b.x, b.y);
                mma16(acc[j][1], Hc[2].x, Hc[3].x, Hc[2].y, Hc[3].y, b.x, b.y);
            }
        }
        __syncwarp();   // GEMM2 h-reads done before epi-2 overwrites h

        // ==== Epilogue 2: +b2, LN, SiLU -> h (in place) ====
        {
            float S[4] = {0, 0, 0, 0}, Q[4] = {0, 0, 0, 0};
            #pragma unroll
            for (int j = 0; j < 16; j++) {
                const float2 bb = *(const float2*)(smf + F_B2 + 8 * j + c0);
                #pragma unroll
                for (int r = 0; r < 4; r++) {
                    float& u = acc[j][r >> 1][(r & 1) * 2];
                    float& w = acc[j][r >> 1][(r & 1) * 2 + 1];
                    u += bb.x; w += bb.y;
                    S[r] += u + w;
                    Q[r] += u * u + w * w;
                }
            }
            #pragma unroll
            for (int m = 1; m <= 2; m <<= 1)
                #pragma unroll
                for (int r = 0; r < 4; r++) {
                    S[r] += __shfl_xor_sync(~0u, S[r], m);
                    Q[r] += __shfl_xor_sync(~0u, Q[r], m);
                }
            float mu[4], rs[4];
            #pragma unroll
            for (int r = 0; r < 4; r++) {
                mu[r] = S[r] * (1.f / H);
                rs[r] = rsqrtf(fmaf(-mu[r], mu[r], Q[r] * (1.f / H)) + LN_EPS);
            }
            #pragma unroll
            for (int j = 0; j < 16; j++) {
                const float2 gg = *(const float2*)(smf + F_G2  + 8 * j + c0);
                const float2 be = *(const float2*)(smf + F_BE2 + 8 * j + c0);
                const int wj = 8 * (j >> 1) + c0 + (j & 1);
                #pragma unroll
                for (int r = 0; r < 4; r++) {
                    const float u = acc[j][r >> 1][(r & 1) * 2];
                    const float w = acc[j][r >> 1][(r & 1) * 2 + 1];
                    hp2[F_H + row[r] * WS + wj] = __floats2half2_rn(
                        silu_f(fmaf((u - mu[r]) * rs[r], gg.x, be.x)),
                        silu_f(fmaf((w - mu[r]) * rs[r], gg.y, be.y)));
                }
            }
        }
        __syncwarp();   // epi-2 writes visible to this warp's GEMM3 loads

        // ==== GEMM3: D3[32,64] = h @ W3^T, K=128 (8 k16-steps, unroll 4) ====
        float a3[8][2][4];
        #pragma unroll
        for (int j = 0; j < 8; j++)
            #pragma unroll
            for (int p = 0; p < 2; p++)
                a3[j][p][0] = a3[j][p][1] = a3[j][p][2] = a3[j][p][3] = 0.f;
        #pragma unroll 4
        for (int s = 0; s < 8; s++) {
            uint2 Hc[4];
            #pragma unroll
            for (int r = 0; r < 4; r++)
                Hc[r] = *(const uint2*)(sm + F_H + row[r] * WS + 8 * s + c0);
            #pragma unroll
            for (int j = 0; j < 8; j++) {
                const uint2 b = *(const uint2*)(sm + F_W3 + (8 * j + g) * WS + 8 * s + c0);
                mma16(a3[j][0], Hc[0].x, Hc[1].x, Hc[0].y, Hc[1].y, b.x, b.y);
                mma16(a3[j][1], Hc[2].x, Hc[3].x, Hc[2].y, Hc[3].y, b.x, b.y);
            }
        }

        // ==== Epilogue 3: +b3, coalesced STG.64 ====
        #pragma unroll
        for (int r = 0; r < 4; r++) {
            if (vr[r]) {
                float* o = out + ((size_t)n * (size_t)E + (size_t)ge[r]) * D_OUT;
                #pragma unroll
                for (int j = 0; j < 8; j++) {
                    const float2 bb = *(const float2*)(smf + F_B3 + 8 * j + c0);
                    float2 v = make_float2(a3[j][r >> 1][(r & 1) * 2]     + bb.x,
                                           a3[j][r >> 1][(r & 1) * 2 + 1] + bb.y);
                    *(float2*)(o + 8 * j + c0) = v;
                }
            }
        }
        // next iteration's first h touch is epi-1, preceded by __syncwarp.
    }
}

} // namespace

extern "C" void kernel_launch(void* const* d_in, const int* in_sizes, int n_in,
                              void* d_out, int out_size) {
    const float* x   = (const float*)d_in[0];
    const float* W1  = (const float*)d_in[1];
    const float* b1  = (const float*)d_in[2];
    const float* g1  = (const float*)d_in[3];
    const float* be1 = (const float*)d_in[4];
    const float* W2  = (const float*)d_in[5];
    const float* b2  = (const float*)d_in[6];
    const float* g2  = (const float*)d_in[7];
    const float* be2 = (const float*)d_in[8];
    const float* W3  = (const float*)d_in[9];
    const float* b3  = (const float*)d_in[10];
    float* out = (float*)d_out;

    const int E = in_sizes[0] / D_IN;
    const int ntiles = (E + TM - 1) / TM;

    cudaFuncSetAttribute(radial_mma,
                         cudaFuncAttributeMaxDynamicSharedMemorySize, SMEM_BYTES);

    radial_mma<<<NBLOCKS, NT, SMEM_BYTES>>>(
        x, W1, b1, g1, be1, W2, b2, g2, be2, W3, b3, out, E, ntiles);
}

// round 13
// speedup vs baseline: 7.6912x; 1.3303x over previous
#include <cuda_runtime.h>
#include <cuda_fp16.h>
#include <cstdint>

// ============================================================================
// UnifiedRadialMLP via mma.sync m16n8k16 f16/f32-acc — base sm_100 PTX.
//
// R12: REGISTER-RESIDENT h. GEMM1's C-fragment layout == GEMM2's A-fragment
// layout (lane (g,t): rows {g,g+8} x cols {8j+2t,8j+2t+1}; step s reads
// j=2s,2s+1). So LN+SiLU output is packed to fp16 in registers and fed
// straight back as A operands: no h SMEM buffer, no epilogue STS, no A-LDS,
// no in-loop syncs. M=16/warp -> ~120 live regs -> __launch_bounds__(256,2):
// 2 CTAs/SM, 16 warps/SM (4/SMSP) vs R11's 11.
// Weights in a paired-step layout: one LDS.128 = B fragments for TWO k16
// steps; row strides == 16 mod 32 words -> quarter-warp spans tile all banks.
// ============================================================================

namespace {

constexpr int D_IN  = 64;
constexpr int H     = 128;
constexpr int D_OUT = 64;
constexpr int MW    = 16;                  // rows per warp
constexpr int NT    = 256;                 // 8 warps
constexpr int TM    = 128;                 // rows per CTA tile
constexpr int SLICES  = 36;
constexpr int NBLOCKS = 8 * SLICES;        // 288 = 2 CTAs/SM x 144 SMs
constexpr float LN_EPS = 1e-5f;

// Row strides in 32-bit words; == 16 mod 32 for conflict-free uint4 loads.
constexpr int W1S = 48;    // K=64:  2 super-blocks (32 words) + 16 pad
constexpr int WS  = 80;    // K=128: 4 super-blocks (64 words) + 16 pad

// SMEM layout (word offsets) — weights + params only (~89 KB)
constexpr int F_W1 = 0;                        // fp16 [128][W1S]
constexpr int F_W2 = F_W1 + H * W1S;           // 6144:  fp16 [128][WS]
constexpr int F_W3 = F_W2 + H * WS;            // 16384: fp16 [64][WS]
constexpr int F_B1 = F_W3 + D_OUT * WS;        // 21504: f32 params
constexpr int F_G1 = F_B1 + H, F_BE1 = F_G1 + H;
constexpr int F_B2 = F_BE1 + H, F_G2 = F_B2 + H, F_BE2 = F_G2 + H;
constexpr int F_B3 = F_BE2 + H;
constexpr int SMEM_WORDS = F_B3 + D_OUT;       // 22336
constexpr int SMEM_BYTES = SMEM_WORDS * 4;     // 89,344 B

// Paired-step half-index permutation. For k in a 32-k super-block sb=k>>5:
//   sp=(k>>4)&1 (step parity), fw=(k>>3)&1 (fragment word), t'=(k&7)>>1, hp=k&1
//   half index = 32sb + 8t' + 4sp + 2fw + hp
// uint4 at word 16sb+4t = (b0 even-step, b1 even-step, b0 odd, b1 odd).
__device__ __forceinline__ int perm32h(int k) {
    return ((k >> 5) << 5) | (((k & 7) >> 1) << 3) | (((k >> 4) & 1) << 2)
         | (((k >> 3) & 1) << 1) | (k & 1);
}

__device__ __forceinline__ void mma16(float d[4],
                                      uint32_t a0, uint32_t a1, uint32_t a2, uint32_t a3,
                                      uint32_t b0, uint32_t b1) {
    asm volatile(
        "mma.sync.aligned.m16n8k16.row.col.f32.f16.f16.f32 "
        "{%0,%1,%2,%3}, {%4,%5,%6,%7}, {%8,%9}, {%0,%1,%2,%3};"
        : "+f"(d[0]), "+f"(d[1]), "+f"(d[2]), "+f"(d[3])
        : "r"(a0), "r"(a1), "r"(a2), "r"(a3), "r"(b0), "r"(b1));
}
__device__ __forceinline__ float silu_f(float v) {
    return __fdividef(v, 1.0f + __expf(-v));
}
__device__ __forceinline__ uint32_t pack2(float lo, float hi) {
    const __half2 h = __floats2half2_rn(lo, hi);
    return *(const uint32_t*)&h;
}

// +bias, LayerNorm, SiLU on acc[16][4] (rows g,g+8 x cols 8j+2t,+1);
// pack results to fp16 A-fragments hA (row g) / hB (row g+8).
__device__ __forceinline__ void epi_ln_pack(float acc[16][4],
                                            uint32_t hA[16], uint32_t hB[16],
                                            const float* __restrict__ smf,
                                            int offB, int offG, int offBE, int c0) {
    float S0 = 0.f, Q0 = 0.f, S1 = 0.f, Q1 = 0.f;
    #pragma unroll
    for (int j = 0; j < 16; j++) {
        const float2 bb = *(const float2*)(smf + offB + 8 * j + c0);
        acc[j][0] += bb.x; acc[j][1] += bb.y;
        acc[j][2] += bb.x; acc[j][3] += bb.y;
        S0 += acc[j][0] + acc[j][1];
        Q0 += acc[j][0] * acc[j][0] + acc[j][1] * acc[j][1];
        S1 += acc[j][2] + acc[j][3];
        Q1 += acc[j][2] * acc[j][2] + acc[j][3] * acc[j][3];
    }
    #pragma unroll
    for (int m = 1; m <= 2; m <<= 1) {
        S0 += __shfl_xor_sync(~0u, S0, m); Q0 += __shfl_xor_sync(~0u, Q0, m);
        S1 += __shfl_xor_sync(~0u, S1, m); Q1 += __shfl_xor_sync(~0u, Q1, m);
    }
    const float mu0 = S0 * (1.f / H), mu1 = S1 * (1.f / H);
    const float rs0 = rsqrtf(fmaf(-mu0, mu0, Q0 * (1.f / H)) + LN_EPS);
    const float rs1 = rsqrtf(fmaf(-mu1, mu1, Q1 * (1.f / H)) + LN_EPS);
    #pragma unroll
    for (int j = 0; j < 16; j++) {
        const float2 gg = *(const float2*)(smf + offG  + 8 * j + c0);
        const float2 be = *(const float2*)(smf + offBE + 8 * j + c0);
        hA[j] = pack2(silu_f(fmaf((acc[j][0] - mu0) * rs0, gg.x, be.x)),
                      silu_f(fmaf((acc[j][1] - mu0) * rs0, gg.y, be.y)));
        hB[j] = pack2(silu_f(fmaf((acc[j][2] - mu1) * rs1, gg.x, be.x)),
                      silu_f(fmaf((acc[j][3] - mu1) * rs1, gg.y, be.y)));
    }
}

__global__ void __launch_bounds__(NT, 2)
radial_mma(const float* __restrict__ x_g,
           const float* __restrict__ W1, const float* __restrict__ b1,
           const float* __restrict__ g1, const float* __restrict__ be1,
           const float* __restrict__ W2, const float* __restrict__ b2,
           const float* __restrict__ g2, const float* __restrict__ be2,
           const float* __restrict__ W3, const float* __restrict__ b3,
           float* __restrict__ out, int E, int ntiles) {
    extern __shared__ uint32_t sm[];
    float*  smf = (float*)sm;
    __half* w1h = (__half*)(sm + F_W1);
    __half* w2h = (__half*)(sm + F_W2);
    __half* w3h = (__half*)(sm + F_W3);

    const int tid  = threadIdx.x;
    const int warp = tid >> 5, lane = tid & 31;
    const int g = lane >> 2, t = lane & 3;
    const int n = blockIdx.x & 7, slice = blockIdx.x >> 3;   // 8 experts x 36
    const int m0 = warp * MW;
    const int c0 = 2 * t;

    // ---- One-time: stage expert weights (fp16, paired-step layout) ----
    for (int i = tid; i < H * D_IN; i += NT) {
        const int r = i >> 6, k = i & 63;
        w1h[r * (2 * W1S) + perm32h(k)] =
            __float2half_rn(W1[(size_t)(n * H + r) * D_IN + k]);
    }
    for (int i = tid; i < H * H; i += NT) {
        const int r = i >> 7, k = i & 127;
        w2h[r * (2 * WS) + perm32h(k)] =
            __float2half_rn(W2[(size_t)n * H * H + (size_t)r * H + k]);
    }
    for (int i = tid; i < D_OUT * H; i += NT) {
        const int r = i >> 7, k = i & 127;
        w3h[r * (2 * WS) + perm32h(k)] =
            __float2half_rn(W3[(size_t)n * D_OUT * H + (size_t)r * H + k]);
    }
    if (tid < H) {
        smf[F_B1 + tid]  = b1 [n * H + tid];
        smf[F_G1 + tid]  = g1 [n * H + tid];
        smf[F_BE1 + tid] = be1[n * H + tid];
        smf[F_B2 + tid]  = b2 [n * H + tid];
        smf[F_G2 + tid]  = g2 [n * H + tid];
        smf[F_BE2 + tid] = be2[n * H + tid];
    }
    if (tid < D_OUT) smf[F_B3 + tid] = b3[n * D_OUT + tid];
    __syncthreads();   // only barrier in the kernel

    for (int tile = slice; tile < ntiles; tile += SLICES) {
        const int e0  = tile * TM;
        const int ge0 = e0 + m0 + g;         // row g
        const int ge1 = ge0 + 8;             // row g+8
        const bool v0 = ge0 < E, v1 = ge1 < E;

        // ==== GEMM1: D1[16,128] = x @ W1^T (2 super-steps) ====
        float acc[16][4];
        #pragma unroll
        for (int j = 0; j < 16; j++)
            acc[j][0] = acc[j][1] = acc[j][2] = acc[j][3] = 0.f;

        #pragma unroll
        for (int sb = 0; sb < 2; sb++) {
            // A fragments for steps 2sb (even) and 2sb+1 (odd), rows g / g+8
            uint32_t ax[2][4];
            #pragma unroll
            for (int r = 0; r < 2; r++) {
                const bool v = r ? v1 : v0;
                if (v) {
                    const float* xr = x_g + (size_t)(r ? ge1 : ge0) * D_IN + 32 * sb;
                    const float2 e_a = *(const float2*)(xr + c0);
                    const float2 e_b = *(const float2*)(xr + c0 + 8);
                    const float2 o_a = *(const float2*)(xr + 16 + c0);
                    const float2 o_b = *(const float2*)(xr + 16 + c0 + 8);
                    ax[r][0] = pack2(e_a.x, e_a.y);
                    ax[r][1] = pack2(e_b.x, e_b.y);
                    ax[r][2] = pack2(o_a.x, o_a.y);
                    ax[r][3] = pack2(o_b.x, o_b.y);
                } else {
                    ax[r][0] = ax[r][1] = ax[r][2] = ax[r][3] = 0u;
                }
            }
            #pragma unroll
            for (int j = 0; j < 16; j++) {
                const uint4 B = *(const uint4*)(sm + F_W1 + (8 * j + g) * W1S
                                                + 16 * sb + 4 * t);
                mma16(acc[j], ax[0][0], ax[1][0], ax[0][1], ax[1][1], B.x, B.y);
                mma16(acc[j], ax[0][2], ax[1][2], ax[0][3], ax[1][3], B.z, B.w);
            }
        }

        // ==== Epilogue 1 -> packed fp16 A-fragments in registers ====
        uint32_t hA[16], hB[16];
        epi_ln_pack(acc, hA, hB, smf, F_B1, F_G1, F_BE1, c0);

        // ==== GEMM2: D2[16,128] = h @ W2^T (4 super-steps) ====
        #pragma unroll
        for (int j = 0; j < 16; j++)
            acc[j][0] = acc[j][1] = acc[j][2] = acc[j][3] = 0.f;
        #pragma unroll
        for (int sb = 0; sb < 4; sb++) {
            #pragma unroll
            for (int j = 0; j < 16; j++) {
                const uint4 B = *(const uint4*)(sm + F_W2 + (8 * j + g) * WS
                                                + 16 * sb + 4 * t);
                mma16(acc[j], hA[4*sb],   hB[4*sb],   hA[4*sb+1], hB[4*sb+1], B.x, B.y);
                mma16(acc[j], hA[4*sb+2], hB[4*sb+2], hA[4*sb+3], hB[4*sb+3], B.z, B.w);
            }
        }

        // ==== Epilogue 2 -> packed fp16 (overwrites hA/hB) ====
        epi_ln_pack(acc, hA, hB, smf, F_B2, F_G2, F_BE2, c0);

        // ==== GEMM3: D3[16,64] = h @ W3^T (4 super-steps) ====
        float a3[8][4];
        #pragma unroll
        for (int j = 0; j < 8; j++)
            a3[j][0] = a3[j][1] = a3[j][2] = a3[j][3] = 0.f;
        #pragma unroll
        for (int sb = 0; sb < 4; sb++) {
            #pragma unroll
            for (int j = 0; j < 8; j++) {
                const uint4 B = *(const uint4*)(sm + F_W3 + (8 * j + g) * WS
                                                + 16 * sb + 4 * t);
                mma16(a3[j], hA[4*sb],   hB[4*sb],   hA[4*sb+1], hB[4*sb+1], B.x, B.y);
                mma16(a3[j], hA[4*sb+2], hB[4*sb+2], hA[4*sb+3], hB[4*sb+3], B.z, B.w);
            }
        }

        // ==== Epilogue 3: +b3, coalesced STG.64 ====
        if (v0) {
            float* o = out + ((size_t)n * (size_t)E + (size_t)ge0) * D_OUT;
            #pragma unroll
            for (int j = 0; j < 8; j++) {
                const float2 bb = *(const float2*)(smf + F_B3 + 8 * j + c0);
                *(float2*)(o + 8 * j + c0) =
                    make_float2(a3[j][0] + bb.x, a3[j][1] + bb.y);
            }
        }
        if (v1) {
            float* o = out + ((size_t)n * (size_t)E + (size_t)ge1) * D_OUT;
            #pragma unroll
            for (int j = 0; j < 8; j++) {
                const float2 bb = *(const float2*)(smf + F_B3 + 8 * j + c0);
                *(float2*)(o + 8 * j + c0) =
                    make_float2(a3[j][2] + bb.x, a3[j][3] + bb.y);
            }
        }
    }
}

} // namespace

extern "C" void kernel_launch(void* const* d_in, const int* in_sizes, int n_in,
                              void* d_out, int out_size) {
    const float* x   = (const float*)d_in[0];
    const float* W1  = (const float*)d_in[1];
    const float* b1  = (const float*)d_in[2];
    const float* g1  = (const float*)d_in[3];
    const float* be1 = (const float*)d_in[4];
    const float* W2  = (const float*)d_in[5];
    const float* b2  = (const float*)d_in[6];
    const float* g2  = (const float*)d_in[7];
    const float* be2 = (const float*)d_in[8];
    const float* W3  = (const float*)d_in[9];
    const float* b3  = (const float*)d_in[10];
    float* out = (float*)d_out;

    const int E = in_sizes[0] / D_IN;
    const int ntiles = (E + TM - 1) / TM;

    cudaFuncSetAttribute(radial_mma,
                         cudaFuncAttributeMaxDynamicSharedMemorySize, SMEM_BYTES);

    radial_mma<<<NBLOCKS, NT, SMEM_BYTES>>>(
        x, W1, b1, g1, be1, W2, b2, g2, be2, W3, b3, out, E, ntiles);
}

// round 14
// speedup vs baseline: 8.8597x; 1.1519x over previous
#include <cuda_runtime.h>
#include <cuda_fp16.h>
#include <cstdint>

// ============================================================================
// UnifiedRadialMLP via mma.sync m16n8k16 f16/f32-acc — base sm_100 PTX.
//
// R13 vs R12 (structure unchanged: register-resident h, M=16/warp,
// 2 CTAs/SM x 8 warps, paired-step LDS.128 weight loads):
//  - SiLU via MUFU.TANH: silu(v) = 0.5v + 0.5v*tanh(0.5v) -> 3 ops/element
//    vs ~8 for the exp+divide chain (fma pipe was 25.8%). tanh.approx.f32
//    error ~1e-5, negligible vs the fp16 rounding already present.
//  - Epilogue 3 j-outer: b3 param loaded once per j for both rows.
// ============================================================================

namespace {

constexpr int D_IN  = 64;
constexpr int H     = 128;
constexpr int D_OUT = 64;
constexpr int MW    = 16;                  // rows per warp
constexpr int NT    = 256;                 // 8 warps
constexpr int TM    = 128;                 // rows per CTA tile
constexpr int SLICES  = 36;
constexpr int NBLOCKS = 8 * SLICES;        // 288 = 2 CTAs/SM x 144 SMs
constexpr float LN_EPS = 1e-5f;

// Row strides in 32-bit words; == 16 mod 32 for conflict-free uint4 loads.
constexpr int W1S = 48;    // K=64:  2 super-blocks (32 words) + 16 pad
constexpr int WS  = 80;    // K=128: 4 super-blocks (64 words) + 16 pad

// SMEM layout (word offsets) — weights + params only (~89 KB)
constexpr int F_W1 = 0;                        // fp16 [128][W1S]
constexpr int F_W2 = F_W1 + H * W1S;           // fp16 [128][WS]
constexpr int F_W3 = F_W2 + H * WS;            // fp16 [64][WS]
constexpr int F_B1 = F_W3 + D_OUT * WS;        // f32 params
constexpr int F_G1 = F_B1 + H, F_BE1 = F_G1 + H;
constexpr int F_B2 = F_BE1 + H, F_G2 = F_B2 + H, F_BE2 = F_G2 + H;
constexpr int F_B3 = F_BE2 + H;
constexpr int SMEM_WORDS = F_B3 + D_OUT;
constexpr int SMEM_BYTES = SMEM_WORDS * 4;     // 89,344 B

// Paired-step half-index permutation. For k in a 32-k super-block sb=k>>5:
//   sp=(k>>4)&1 (step parity), fw=(k>>3)&1 (fragment word), t'=(k&7)>>1, hp=k&1
//   half index = 32sb + 8t' + 4sp + 2fw + hp
// uint4 at word 16sb+4t = (b0 even-step, b1 even-step, b0 odd, b1 odd).
__device__ __forceinline__ int perm32h(int k) {
    return ((k >> 5) << 5) | (((k & 7) >> 1) << 3) | (((k >> 4) & 1) << 2)
         | (((k >> 3) & 1) << 1) | (k & 1);
}

__device__ __forceinline__ void mma16(float d[4],
                                      uint32_t a0, uint32_t a1, uint32_t a2, uint32_t a3,
                                      uint32_t b0, uint32_t b1) {
    asm volatile(
        "mma.sync.aligned.m16n8k16.row.col.f32.f16.f16.f32 "
        "{%0,%1,%2,%3}, {%4,%5,%6,%7}, {%8,%9}, {%0,%1,%2,%3};"
        : "+f"(d[0]), "+f"(d[1]), "+f"(d[2]), "+f"(d[3])
        : "r"(a0), "r"(a1), "r"(a2), "r"(a3), "r"(b0), "r"(b1));
}
// silu(v) = v*sigmoid(v) = 0.5v*(1+tanh(0.5v)) : 1 FMUL + 1 MUFU.TANH + 1 FFMA
__device__ __forceinline__ float silu_f(float v) {
    const float hv = 0.5f * v;
    float th;
    asm("tanh.approx.f32 %0, %1;" : "=f"(th) : "f"(hv));
    return fmaf(hv, th, hv);
}
__device__ __forceinline__ uint32_t pack2(float lo, float hi) {
    const __half2 h = __floats2half2_rn(lo, hi);
    return *(const uint32_t*)&h;
}

// +bias, LayerNorm, SiLU on acc[16][4] (rows g,g+8 x cols 8j+2t,+1);
// pack results to fp16 A-fragments hA (row g) / hB (row g+8).
__device__ __forceinline__ void epi_ln_pack(float acc[16][4],
                                            uint32_t hA[16], uint32_t hB[16],
                                            const float* __restrict__ smf,
                                            int offB, int offG, int offBE, int c0) {
    float S0 = 0.f, Q0 = 0.f, S1 = 0.f, Q1 = 0.f;
    #pragma unroll
    for (int j = 0; j < 16; j++) {
        const float2 bb = *(const float2*)(smf + offB + 8 * j + c0);
        acc[j][0] += bb.x; acc[j][1] += bb.y;
        acc[j][2] += bb.x; acc[j][3] += bb.y;
        S0 += acc[j][0] + acc[j][1];
        Q0 += acc[j][0] * acc[j][0] + acc[j][1] * acc[j][1];
        S1 += acc[j][2] + acc[j][3];
        Q1 += acc[j][2] * acc[j][2] + acc[j][3] * acc[j][3];
    }
    #pragma unroll
    for (int m = 1; m <= 2; m <<= 1) {
        S0 += __shfl_xor_sync(~0u, S0, m); Q0 += __shfl_xor_sync(~0u, Q0, m);
        S1 += __shfl_xor_sync(~0u, S1, m); Q1 += __shfl_xor_sync(~0u, Q1, m);
    }
    const float mu0 = S0 * (1.f / H), mu1 = S1 * (1.f / H);
    const float rs0 = rsqrtf(fmaf(-mu0, mu0, Q0 * (1.f / H)) + LN_EPS);
    const float rs1 = rsqrtf(fmaf(-mu1, mu1, Q1 * (1.f / H)) + LN_EPS);
    #pragma unroll
    for (int j = 0; j < 16; j++) {
        const float2 gg = *(const float2*)(smf + offG  + 8 * j + c0);
        const float2 be = *(const float2*)(smf + offBE + 8 * j + c0);
        hA[j] = pack2(silu_f(fmaf((acc[j][0] - mu0) * rs0, gg.x, be.x)),
                      silu_f(fmaf((acc[j][1] - mu0) * rs0, gg.y, be.y)));
        hB[j] = pack2(silu_f(fmaf((acc[j][2] - mu1) * rs1, gg.x, be.x)),
                      silu_f(fmaf((acc[j][3] - mu1) * rs1, gg.y, be.y)));
    }
}

__global__ void __launch_bounds__(NT, 2)
radial_mma(const float* __restrict__ x_g,
           const float* __restrict__ W1, const float* __restrict__ b1,
           const float* __restrict__ g1, const float* __restrict__ be1,
           const float* __restrict__ W2, const float* __restrict__ b2,
           const float* __restrict__ g2, const float* __restrict__ be2,
           const float* __restrict__ W3, const float* __restrict__ b3,
           float* __restrict__ out, int E, int ntiles) {
    extern __shared__ uint32_t sm[];
    float*  smf = (float*)sm;
    __half* w1h = (__half*)(sm + F_W1);
    __half* w2h = (__half*)(sm + F_W2);
    __half* w3h = (__half*)(sm + F_W3);

    const int tid  = threadIdx.x;
    const int warp = tid >> 5, lane = tid & 31;
    const int g = lane >> 2, t = lane & 3;
    const int n = blockIdx.x & 7, slice = blockIdx.x >> 3;   // 8 experts x 36
    const int m0 = warp * MW;
    const int c0 = 2 * t;

    // ---- One-time: stage expert weights (fp16, paired-step layout) ----
    for (int i = tid; i < H * D_IN; i += NT) {
        const int r = i >> 6, k = i & 63;
        w1h[r * (2 * W1S) + perm32h(k)] =
            __float2half_rn(W1[(size_t)(n * H + r) * D_IN + k]);
    }
    for (int i = tid; i < H * H; i += NT) {
        const int r = i >> 7, k = i & 127;
        w2h[r * (2 * WS) + perm32h(k)] =
            __float2half_rn(W2[(size_t)n * H * H + (size_t)r * H + k]);
    }
    for (int i = tid; i < D_OUT * H; i += NT) {
        const int r = i >> 7, k = i & 127;
        w3h[r * (2 * WS) + perm32h(k)] =
            __float2half_rn(W3[(size_t)n * D_OUT * H + (size_t)r * H + k]);
    }
    if (tid < H) {
        smf[F_B1 + tid]  = b1 [n * H + tid];
        smf[F_G1 + tid]  = g1 [n * H + tid];
        smf[F_BE1 + tid] = be1[n * H + tid];
        smf[F_B2 + tid]  = b2 [n * H + tid];
        smf[F_G2 + tid]  = g2 [n * H + tid];
        smf[F_BE2 + tid] = be2[n * H + tid];
    }
    if (tid < D_OUT) smf[F_B3 + tid] = b3[n * D_OUT + tid];
    __syncthreads();   // only barrier in the kernel

    for (int tile = slice; tile < ntiles; tile += SLICES) {
        const int e0  = tile * TM;
        const int ge0 = e0 + m0 + g;         // row g
        const int ge1 = ge0 + 8;             // row g+8
        const bool v0 = ge0 < E, v1 = ge1 < E;

        // ==== GEMM1: D1[16,128] = x @ W1^T (2 super-steps) ====
        float acc[16][4];
        #pragma unroll
        for (int j = 0; j < 16; j++)
            acc[j][0] = acc[j][1] = acc[j][2] = acc[j][3] = 0.f;

        #pragma unroll
        for (int sb = 0; sb < 2; sb++) {
            // A fragments for steps 2sb (even) and 2sb+1 (odd), rows g / g+8
            uint32_t ax[2][4];
            #pragma unroll
            for (int r = 0; r < 2; r++) {
                const bool v = r ? v1 : v0;
                if (v) {
                    const float* xr = x_g + (size_t)(r ? ge1 : ge0) * D_IN + 32 * sb;
                    const float2 e_a = *(const float2*)(xr + c0);
                    const float2 e_b = *(const float2*)(xr + c0 + 8);
                    const float2 o_a = *(const float2*)(xr + 16 + c0);
                    const float2 o_b = *(const float2*)(xr + 16 + c0 + 8);
                    ax[r][0] = pack2(e_a.x, e_a.y);
                    ax[r][1] = pack2(e_b.x, e_b.y);
                    ax[r][2] = pack2(o_a.x, o_a.y);
                    ax[r][3] = pack2(o_b.x, o_b.y);
                } else {
                    ax[r][0] = ax[r][1] = ax[r][2] = ax[r][3] = 0u;
                }
            }
            #pragma unroll
            for (int j = 0; j < 16; j++) {
                const uint4 B = *(const uint4*)(sm + F_W1 + (8 * j + g) * W1S
                                                + 16 * sb + 4 * t);
                mma16(acc[j], ax[0][0], ax[1][0], ax[0][1], ax[1][1], B.x, B.y);
                mma16(acc[j], ax[0][2], ax[1][2], ax[0][3], ax[1][3], B.z, B.w);
            }
        }

        // ==== Epilogue 1 -> packed fp16 A-fragments in registers ====
        uint32_t hA[16], hB[16];
        epi_ln_pack(acc, hA, hB, smf, F_B1, F_G1, F_BE1, c0);

        // ==== GEMM2: D2[16,128] = h @ W2^T (4 super-steps) ====
        #pragma unroll
        for (int j = 0; j < 16; j++)
            acc[j][0] = acc[j][1] = acc[j][2] = acc[j][3] = 0.f;
        #pragma unroll
        for (int sb = 0; sb < 4; sb++) {
            #pragma unroll
            for (int j = 0; j < 16; j++) {
                const uint4 B = *(const uint4*)(sm + F_W2 + (8 * j + g) * WS
                                                + 16 * sb + 4 * t);
                mma16(acc[j], hA[4*sb],   hB[4*sb],   hA[4*sb+1], hB[4*sb+1], B.x, B.y);
                mma16(acc[j], hA[4*sb+2], hB[4*sb+2], hA[4*sb+3], hB[4*sb+3], B.z, B.w);
            }
        }

        // ==== Epilogue 2 -> packed fp16 (overwrites hA/hB) ====
        epi_ln_pack(acc, hA, hB, smf, F_B2, F_G2, F_BE2, c0);

        // ==== GEMM3: D3[16,64] = h @ W3^T (4 super-steps) ====
        float a3[8][4];
        #pragma unroll
        for (int j = 0; j < 8; j++)
            a3[j][0] = a3[j][1] = a3[j][2] = a3[j][3] = 0.f;
        #pragma unroll
        for (int sb = 0; sb < 4; sb++) {
            #pragma unroll
            for (int j = 0; j < 8; j++) {
                const uint4 B = *(const uint4*)(sm + F_W3 + (8 * j + g) * WS
                                                + 16 * sb + 4 * t);
                mma16(a3[j], hA[4*sb],   hB[4*sb],   hA[4*sb+1], hB[4*sb+1], B.x, B.y);
                mma16(a3[j], hA[4*sb+2], hB[4*sb+2], hA[4*sb+3], hB[4*sb+3], B.z, B.w);
            }
        }

        // ==== Epilogue 3: +b3, coalesced STG.64 (j-outer: b3 loaded once) ====
        {
            float* o0 = out + ((size_t)n * (size_t)E + (size_t)ge0) * D_OUT;
            float* o1 = out + ((size_t)n * (size_t)E + (size_t)ge1) * D_OUT;
            #pragma unroll
            for (int j = 0; j < 8; j++) {
                const float2 bb = *(const float2*)(smf + F_B3 + 8 * j + c0);
                if (v0)
                    *(float2*)(o0 + 8 * j + c0) =
                        make_float2(a3[j][0] + bb.x, a3[j][1] + bb.y);
                if (v1)
                    *(float2*)(o1 + 8 * j + c0) =
                        make_float2(a3[j][2] + bb.x, a3[j][3] + bb.y);
            }
        }
    }
}

} // namespace

extern "C" void kernel_launch(void* const* d_in, const int* in_sizes, int n_in,
                              void* d_out, int out_size) {
    const float* x   = (const float*)d_in[0];
    const float* W1  = (const float*)d_in[1];
    const float* b1  = (const float*)d_in[2];
    const float* g1  = (const float*)d_in[3];
    const float* be1 = (const float*)d_in[4];
    const float* W2  = (const float*)d_in[5];
    const float* b2  = (const float*)d_in[6];
    const float* g2  = (const float*)d_in[7];
    const float* be2 = (const float*)d_in[8];
    const float* W3  = (const float*)d_in[9];
    const float* b3  = (const float*)d_in[10];
    float* out = (float*)d_out;

    const int E = in_sizes[0] / D_IN;
    const int ntiles = (E + TM - 1) / TM;

    cudaFuncSetAttribute(radial_mma,
                         cudaFuncAttributeMaxDynamicSharedMemorySize, SMEM_BYTES);

    radial_mma<<<NBLOCKS, NT, SMEM_BYTES>>>(
        x, W1, b1, g1, be1, W2, b2, g2, be2, W3, b3, out, E, ntiles);
}